// round 10
// baseline (speedup 1.0000x reference)
#include <cuda_runtime.h>
#include <cuda_bf16.h>
#include <cstdint>
#include <cstddef>
#include <math.h>

// ---------------------------------------------------------------------------
// Problem constants
// ---------------------------------------------------------------------------
#define T_SEQ   2048
#define HID     256
#define GATES   1024      // 4*HID
#define IN_DIM  22
#define D_H1    1024
#define D_H2    512
#define D_H3    1024
#define NPAIRS  65536

#define SENTINEL 0xFFFFFFFFu

// ---------------------------------------------------------------------------
// Scratch (device globals — allocation is forbidden)
// ---------------------------------------------------------------------------
__device__ float g_PRE [4 * T_SEQ * GATES];
__device__ float g_h0  [2 * T_SEQ * 512];
__device__ float g_h1  [2 * T_SEQ * 512];
__device__ float g_fc1 [2 * T_SEQ * D_H1];
__device__ float g_enc [2 * T_SEQ * D_H2];
__device__ float g_P   [2 * T_SEQ * D_H3];
__device__ float g_Ws  [D_H3 * D_H2];
__device__ float g_bs  [2 * GATES];

// ---------------------------------------------------------------------------
// Fast nonlinearities (MUFU-backed, ~1e-7 rel err)
// ---------------------------------------------------------------------------
__device__ __forceinline__ float sig_f(float x)
{
    return __fdividef(1.f, 1.f + __expf(-x));
}
__device__ __forceinline__ float tanh_f(float x)
{
    return __fdividef(2.f, 1.f + __expf(-2.f * x)) - 1.f;
}

// ---------------------------------------------------------------------------
// Re-sentinel the LSTM output buffers (inside the graph, every replay)
// ---------------------------------------------------------------------------
__global__ void init_sent_kernel()
{
    unsigned idx = blockIdx.x * blockDim.x + threadIdx.x;
    const unsigned total = 2u * T_SEQ * 512u;
    if (idx < total) {
        ((unsigned*)g_h0)[idx] = SENTINEL;
        ((unsigned*)g_h1)[idx] = SENTINEL;
    }
}

// ---------------------------------------------------------------------------
// Layer-0 input gates, 16 timesteps per CTA (weights register-resident).
// grid (4, 128, 4), block 256
// ---------------------------------------------------------------------------
__global__ void __launch_bounds__(256) pre0_kernel(
    const float* __restrict__ v_r, const float* __restrict__ v_l,
    const float* __restrict__ Wih0,
    const float* __restrict__ bih0, const float* __restrict__ bhh0)
{
    const int g     = blockIdx.x * 256 + threadIdx.x;   // 0..1023
    const int tbase = blockIdx.y * 16;
    const int seq   = blockIdx.z;
    const int chain = seq >> 1, dir = seq & 1;

    __shared__ float vs[16][IN_DIM + 2];
    const float* v = (chain ? v_l : v_r) + (size_t)tbase * IN_DIM;
    for (int i = threadIdx.x; i < 16 * IN_DIM; i += 256)
        vs[i / IN_DIM][i % IN_DIM] = v[i];
    __syncthreads();

    float wr[IN_DIM];
    const float* wp = Wih0 + ((size_t)dir * GATES + g) * IN_DIM;
#pragma unroll
    for (int k = 0; k < IN_DIM; k++) wr[k] = __ldg(wp + k);
    const float b = bih0[dir * GATES + g] + bhh0[dir * GATES + g];

    float* outp = g_PRE + ((size_t)seq * T_SEQ + tbase) * GATES + g;
#pragma unroll
    for (int tt = 0; tt < 16; tt++) {
        float s = b;
#pragma unroll
        for (int k = 0; k < IN_DIM; k++) s = fmaf(wr[k], vs[tt][k], s);
        outp[(size_t)tt * GATES] = s;
    }
}

// ---------------------------------------------------------------------------
// Combined layer-1 biases / Ws = W3[:, :H2] + W3[:, H2:]
// ---------------------------------------------------------------------------
__global__ void bsum_kernel(const float* __restrict__ bih1,
                            const float* __restrict__ bhh1)
{
    int i = blockIdx.x * 256 + threadIdx.x;
    if (i < 2 * GATES) g_bs[i] = bih1[i] + bhh1[i];
}

__global__ void ws_kernel(const float* __restrict__ W3)
{
    int idx = blockIdx.x * 256 + threadIdx.x;
    if (idx < D_H3 * D_H2) {
        int i = idx >> 9;
        int j = idx & 511;
        g_Ws[idx] = W3[(size_t)i * (2 * D_H2) + j]
                  + W3[(size_t)i * (2 * D_H2) + D_H2 + j];
    }
}

// ---------------------------------------------------------------------------
// BiLSTM layer. grid = 32 CTAs, block 256. Each CTA: chunk c (16 hidden
// units) of TWO independent sequences — half 0 = threads 0..127, half 1 =
// threads 128..255, synchronized with separate named barriers so one half's
// sentinel-poll stall overlaps the other half's FFMA stream.
//
// Per-half lane layout (warp w4 of 4, lane l):
//   rr = l & 15, khalf = l >> 4
//   unit u = w4*4 + (rr>>2), gate g = rr&3  ->  grow = g*256 + c*16 + u
// Row sum = shfl_xor(.,16); gate gather = 3 shfl from adjacent lanes.
// h_s double-buffered by step parity -> exactly 1 named barrier per step.
// ---------------------------------------------------------------------------
__global__ void __launch_bounds__(256, 1) lstm_kernel(
    const float* __restrict__ PRE,    // [4][T][1024]
    const float* __restrict__ Whh,    // [2][1024][256]
    float* __restrict__ HB)           // [2][T][512], sentinel-initialized
{
    const int bx    = blockIdx.x;          // 0..31
    const int grp   = bx >> 4;             // 0/1
    const int c     = bx & 15;             // chunk 0..15
    const int tid   = threadIdx.x;
    const int half  = tid >> 7;            // 0/1
    const int ht    = tid & 127;
    const int seq   = grp + (half << 1);   // {0,2} or {1,3}
    const int chain = seq >> 1, dir = seq & 1;

    const int w4    = ht >> 5;             // warp within half, 0..3
    const int lane  = tid & 31;
    const int rr    = lane & 15;
    const int khalf = lane >> 4;           // K range [khalf*128, +128)
    const int u     = (w4 << 2) + (rr >> 2);        // unit 0..15
    const int g     = rr & 3;                       // gate (i,f,g,o)
    const int grow  = (g << 8) + (c << 4) + u;      // global gate row

    __shared__ __align__(16) float h_s[2][2][256];  // [half][parity][comp]

    // Recurrent weights for this (row, K-half) in registers.
    float w[128];
    {
        const float* wp = Whh + ((size_t)dir * GATES + grow) * HID + khalf * 128;
#pragma unroll
        for (int i = 0; i < 128; i += 4) {
            float4 v = *(const float4*)(wp + i);
            w[i] = v.x; w[i + 1] = v.y; w[i + 2] = v.z; w[i + 3] = v.w;
        }
    }

    float* hbc = HB + (size_t)chain * T_SEQ * 512;
    const float* prebase = PRE + (size_t)seq * T_SEQ * GATES + grow;

    const int  i0     = ht << 1;                 // polled components i0, i0+1
    const bool own    = ((i0 >> 4) == c);        // produced locally
    const bool isprod = (khalf == 0) && (g == 0);
    float cstate = 0.f;                          // valid for producer lanes

    // Zero both parity buffers (h_{-1} = 0)
    h_s[half][0][ht] = 0.f; h_s[half][0][ht + 128] = 0.f;
    h_s[half][1][ht] = 0.f; h_s[half][1][ht + 128] = 0.f;
    asm volatile("bar.sync %0, 128;" :: "r"(1 + half));

    for (int t = 0; t < T_SEQ; t++) {
        const int t_act = dir ? (T_SEQ - 1 - t) : t;
        const int par   = t & 1;

        // Input-gate prefetch (independent of h, overlaps the poll)
        float preval = 0.f;
        if (khalf == 0)
            preval = __ldg(prebase + (size_t)t_act * GATES);

        if (t > 0 && !own) {
            const int p_act = dir ? (t_act + 1) : (t_act - 1);
            const unsigned* pp =
                (const unsigned*)(hbc + (size_t)p_act * 512 + dir * 256 + i0);
            unsigned v0, v1;
            do { asm volatile("ld.volatile.global.u32 %0, [%1];"
                              : "=r"(v0) : "l"(pp)); } while (v0 == SENTINEL);
            do { asm volatile("ld.volatile.global.u32 %0, [%1];"
                              : "=r"(v1) : "l"(pp + 1)); } while (v1 == SENTINEL);
            h_s[half][par][i0]     = __uint_as_float(v0);
            h_s[half][par][i0 + 1] = __uint_as_float(v1);
        }
        asm volatile("bar.sync %0, 128;" :: "r"(1 + half));

        // 128-MAC partial matvec over smem-broadcast h (4 accumulators)
        const float* hp = &h_s[half][par][khalf << 7];
        float a0 = 0.f, a1 = 0.f, a2 = 0.f, a3 = 0.f;
#pragma unroll
        for (int i = 0; i < 128; i += 4) {
            float4 hv = *(const float4*)(hp + i);
            a0 = fmaf(w[i],     hv.x, a0);
            a1 = fmaf(w[i + 1], hv.y, a1);
            a2 = fmaf(w[i + 2], hv.z, a2);
            a3 = fmaf(w[i + 3], hv.w, a3);
        }
        float a = (a0 + a1) + (a2 + a3);
        if (khalf == 0) a += preval;
        a += __shfl_xor_sync(0xFFFFFFFFu, a, 16);   // sum K-halves (full row)

        // Gather the 4 gates of this thread's unit from adjacent lanes
        float gf = __shfl_sync(0xFFFFFFFFu, a, (lane & ~3) | 1, 32);
        float gg = __shfl_sync(0xFFFFFFFFu, a, (lane & ~3) | 2, 32);
        float go = __shfl_sync(0xFFFFFFFFu, a, (lane & ~3) | 3, 32);

        if (isprod) {
            float gi = a;
            cstate = sig_f(gf) * cstate + sig_f(gi) * tanh_f(gg);
            float h = sig_f(go) * tanh_f(cstate);
            h_s[half][par ^ 1][(c << 4) + u] = h;     // next step's buffer
            unsigned hv = __float_as_uint(h);
            unsigned* dst = (unsigned*)(hbc + (size_t)t_act * 512
                                        + dir * 256 + (c << 4) + u);
            asm volatile("st.volatile.global.u32 [%0], %1;" :: "l"(dst), "r"(hv));
        }
    }
}

// ---------------------------------------------------------------------------
// SGEMM: C = act( alpha * ( A[M,K] @ B[N,K]^T + bias[N] ) )
// 128x128 tile, BK=8, 256 threads, 8x8 microtile, register-prefetched K tile.
// Batched via blockIdx.z: A += (z/aDiv)*sA; B += (z%bMod)*sB;
//                         bias += (z%bMod)*sBias; C += z*sC
// ---------------------------------------------------------------------------
__global__ void __launch_bounds__(256) gemm_kernel(
    const float* __restrict__ A, const float* __restrict__ B,
    const float* __restrict__ bias, float* __restrict__ C,
    int M, int N, int K, float alpha, int relu,
    long sA, long sB, long sBias, long sC, int aDiv, int bMod)
{
    A    += (size_t)(blockIdx.z / aDiv) * sA;
    B    += (size_t)(blockIdx.z % bMod) * sB;
    bias += (size_t)(blockIdx.z % bMod) * sBias;
    C    += (size_t)blockIdx.z * sC;

    __shared__ __align__(16) float As[8][132];
    __shared__ __align__(16) float Bs[8][132];

    const int tid = threadIdx.x;
    const int tx = tid & 15, ty = tid >> 4;
    const int m0 = blockIdx.y * 128, n0 = blockIdx.x * 128;
    const int lrow = tid >> 1;
    const int lk   = (tid & 1) << 2;

    float acc[8][8];
#pragma unroll
    for (int i = 0; i < 8; i++)
#pragma unroll
        for (int j = 0; j < 8; j++) acc[i][j] = 0.f;

    const float* Ap = A + (size_t)(m0 + lrow) * K + lk;
    const float* Bp = B + (size_t)(n0 + lrow) * K + lk;

    float4 av = *(const float4*)(Ap);
    float4 bv = *(const float4*)(Bp);

    for (int k0 = 0; k0 < K; k0 += 8) {
        __syncthreads();
        As[lk + 0][lrow] = av.x; As[lk + 1][lrow] = av.y;
        As[lk + 2][lrow] = av.z; As[lk + 3][lrow] = av.w;
        Bs[lk + 0][lrow] = bv.x; Bs[lk + 1][lrow] = bv.y;
        Bs[lk + 2][lrow] = bv.z; Bs[lk + 3][lrow] = bv.w;
        __syncthreads();

        if (k0 + 8 < K) {                    // prefetch next K tile
            av = *(const float4*)(Ap + k0 + 8);
            bv = *(const float4*)(Bp + k0 + 8);
        }

#pragma unroll
        for (int kk = 0; kk < 8; kk++) {
            float4 a0 = *(const float4*)&As[kk][tx << 2];
            float4 a1 = *(const float4*)&As[kk][64 + (tx << 2)];
            float4 b0 = *(const float4*)&Bs[kk][ty << 2];
            float4 b1 = *(const float4*)&Bs[kk][64 + (ty << 2)];
            float ar[8] = {a0.x, a0.y, a0.z, a0.w, a1.x, a1.y, a1.z, a1.w};
            float br[8] = {b0.x, b0.y, b0.z, b0.w, b1.x, b1.y, b1.z, b1.w};
#pragma unroll
            for (int i = 0; i < 8; i++)
#pragma unroll
                for (int j = 0; j < 8; j++)
                    acc[i][j] = fmaf(ar[i], br[j], acc[i][j]);
        }
    }

    float bia[8];
#pragma unroll
    for (int j = 0; j < 8; j++) {
        int n = n0 + ((j < 4) ? (ty << 2) + j : 64 + (ty << 2) + (j - 4));
        bia[j] = bias[n];
    }

#pragma unroll
    for (int i = 0; i < 8; i++) {
        int m = m0 + ((i < 4) ? (tx << 2) + i : 64 + (tx << 2) + (i - 4));
        float v[8];
#pragma unroll
        for (int j = 0; j < 8; j++) {
            float x = alpha * (acc[i][j] + bia[j]);
            v[j] = relu ? fmaxf(x, 0.f) : x;
        }
        float4 o0 = {v[0], v[1], v[2], v[3]};
        float4 o1 = {v[4], v[5], v[6], v[7]};
        *(float4*)(C + (size_t)m * N + n0 + (ty << 2))      = o0;
        *(float4*)(C + (size_t)m * N + n0 + 64 + (ty << 2)) = o1;
    }
}

// ---------------------------------------------------------------------------
// Pair stage: logits[p] = relu(P_r[pr] + P_l[pl]) . Wout^T + bout; log_softmax
// ---------------------------------------------------------------------------
__global__ void __launch_bounds__(256) pair_kernel(
    const int* __restrict__ pair_r, const int* __restrict__ pair_l,
    const float* __restrict__ Wout, const float* __restrict__ bout,
    float* __restrict__ out)
{
    __shared__ float w0[D_H3], w1[D_H3];
    for (int i = threadIdx.x; i < D_H3; i += 256) {
        w0[i] = Wout[i];
        w1[i] = Wout[D_H3 + i];
    }
    __syncthreads();

    const int warp = threadIdx.x >> 5, lane = threadIdx.x & 31;
    const float b0 = bout[0], b1 = bout[1];
    const float* Pr_base = g_P;
    const float* Pl_base = g_P + (size_t)T_SEQ * D_H3;

    for (int p = blockIdx.x * 8 + warp; p < NPAIRS; p += gridDim.x * 8) {
        const float4* Pr = (const float4*)(Pr_base + (size_t)pair_r[p] * D_H3);
        const float4* Pl = (const float4*)(Pl_base + (size_t)pair_l[p] * D_H3);
        float a0 = 0.f, a1 = 0.f;
#pragma unroll 4
        for (int k4 = lane; k4 < D_H3 / 4; k4 += 32) {
            float4 r = __ldg(Pr + k4);
            float4 l = __ldg(Pl + k4);
            int kb = k4 << 2;
            float s0 = fmaxf(r.x + l.x, 0.f);
            float s1 = fmaxf(r.y + l.y, 0.f);
            float s2 = fmaxf(r.z + l.z, 0.f);
            float s3 = fmaxf(r.w + l.w, 0.f);
            a0 = fmaf(s0, w0[kb], a0);     a1 = fmaf(s0, w1[kb], a1);
            a0 = fmaf(s1, w0[kb + 1], a0); a1 = fmaf(s1, w1[kb + 1], a1);
            a0 = fmaf(s2, w0[kb + 2], a0); a1 = fmaf(s2, w1[kb + 2], a1);
            a0 = fmaf(s3, w0[kb + 3], a0); a1 = fmaf(s3, w1[kb + 3], a1);
        }
#pragma unroll
        for (int off = 16; off > 0; off >>= 1) {
            a0 += __shfl_down_sync(0xFFFFFFFFu, a0, off);
            a1 += __shfl_down_sync(0xFFFFFFFFu, a1, off);
        }
        if (lane == 0) {
            float l0 = a0 + b0, l1 = a1 + b1;
            float m = fmaxf(l0, l1);
            float lse = m + logf(expf(l0 - m) + expf(l1 - m));
            out[2 * p]     = l0 - lse;
            out[2 * p + 1] = l1 - lse;
        }
    }
}

// ---------------------------------------------------------------------------
// Host
// ---------------------------------------------------------------------------
extern "C" void kernel_launch(void* const* d_in, const int* in_sizes, int n_in,
                              void* d_out, int out_size)
{
    const float* v_r    = (const float*)d_in[0];
    const float* v_l    = (const float*)d_in[1];
    const int*   pair_r = (const int*)  d_in[2];
    const int*   pair_l = (const int*)  d_in[3];
    const float* Wih0   = (const float*)d_in[4];
    const float* Whh0   = (const float*)d_in[5];
    const float* bih0   = (const float*)d_in[6];
    const float* bhh0   = (const float*)d_in[7];
    const float* Wih1   = (const float*)d_in[8];
    const float* Whh1   = (const float*)d_in[9];
    const float* bih1   = (const float*)d_in[10];
    const float* bhh1   = (const float*)d_in[11];
    const float* W1     = (const float*)d_in[12];
    const float* b1     = (const float*)d_in[13];
    const float* W2     = (const float*)d_in[14];
    const float* b2     = (const float*)d_in[15];
    const float* W3     = (const float*)d_in[16];
    const float* b3     = (const float*)d_in[17];
    const float* Wout   = (const float*)d_in[18];
    const float* bout   = (const float*)d_in[19];
    float* out = (float*)d_out;

    float *PRE, *H0, *H1, *FC1, *ENC, *PT, *WS, *BS;
    cudaGetSymbolAddress((void**)&PRE, g_PRE);
    cudaGetSymbolAddress((void**)&H0,  g_h0);
    cudaGetSymbolAddress((void**)&H1,  g_h1);
    cudaGetSymbolAddress((void**)&FC1, g_fc1);
    cudaGetSymbolAddress((void**)&ENC, g_enc);
    cudaGetSymbolAddress((void**)&PT,  g_P);
    cudaGetSymbolAddress((void**)&WS,  g_Ws);
    cudaGetSymbolAddress((void**)&BS,  g_bs);

    // 1. Sentinel-init LSTM output buffers (every replay)
    init_sent_kernel<<<(2 * T_SEQ * 512 + 255) / 256, 256>>>();

    // 2. Small precomputes
    pre0_kernel<<<dim3(4, 128, 4), 256>>>(v_r, v_l, Wih0, bih0, bhh0);
    bsum_kernel<<<8, 256>>>(bih1, bhh1);
    ws_kernel<<<(D_H3 * D_H2 + 255) / 256, 256>>>(W3);

    // 3. LSTM layer 0 (32 CTAs: 16 chunks x 2 sequence-pairs)
    lstm_kernel<<<32, 256>>>(PRE, Whh0, H0);

    // 4. Layer-1 input gates, batched over seq (z=4):
    //    PRE[seq] = H0[chain] @ Wih1[dir]^T + (bih1+bhh1)[dir]
    gemm_kernel<<<dim3(GATES / 128, T_SEQ / 128, 4), 256>>>(
        H0, Wih1, BS, PRE, T_SEQ, GATES, 512, 1.f, 0,
        (long)T_SEQ * 512, (long)GATES * 512, (long)GATES,
        (long)T_SEQ * GATES, 2, 2);

    // 5. LSTM layer 1
    lstm_kernel<<<32, 256>>>(PRE, Whh1, H1);

    // 6. MLP encoders, batched over chain (z=2)
    gemm_kernel<<<dim3(D_H1 / 128, T_SEQ / 128, 2), 256>>>(
        H1, W1, b1, FC1, T_SEQ, D_H1, 512, 1.f, 1,
        (long)T_SEQ * 512, 0, 0, (long)T_SEQ * D_H1, 1, 1);

    gemm_kernel<<<dim3(D_H2 / 128, T_SEQ / 128, 2), 256>>>(
        FC1, W2, b2, ENC, T_SEQ, D_H2, D_H1, 1.f, 1,
        (long)T_SEQ * D_H1, 0, 0, (long)T_SEQ * D_H2, 1, 1);

    // P = 0.5*(enc @ Ws^T + b3)
    gemm_kernel<<<dim3(D_H3 / 128, T_SEQ / 128, 2), 256>>>(
        ENC, WS, b3, PT, T_SEQ, D_H3, D_H2, 0.5f, 0,
        (long)T_SEQ * D_H2, 0, 0, (long)T_SEQ * D_H3, 1, 1);

    // 7. Pair gather + dot + log_softmax
    pair_kernel<<<2048, 256>>>(pair_r, pair_l, Wout, bout, out);
}

// round 11
// speedup vs baseline: 1.0293x; 1.0293x over previous
#include <cuda_runtime.h>
#include <cuda_bf16.h>
#include <cstdint>
#include <cstddef>
#include <math.h>

// ---------------------------------------------------------------------------
// Problem constants
// ---------------------------------------------------------------------------
#define T_SEQ   2048
#define HID     256
#define GATES   1024      // 4*HID
#define IN_DIM  22
#define D_H1    1024
#define D_H2    512
#define D_H3    1024
#define NPAIRS  65536

#define SENTINEL 0xFFFFFFFFu

// ---------------------------------------------------------------------------
// Scratch (device globals — allocation is forbidden)
// ---------------------------------------------------------------------------
__device__ float g_PRE [4 * T_SEQ * GATES];
__device__ float g_h0  [2 * T_SEQ * 512];
__device__ float g_h1  [2 * T_SEQ * 512];
__device__ float g_fc1 [2 * T_SEQ * D_H1];
__device__ float g_enc [2 * T_SEQ * D_H2];
__device__ float g_P   [2 * T_SEQ * D_H3];
__device__ float g_Ws  [D_H3 * D_H2];
__device__ float g_bs  [2 * GATES];

// ---------------------------------------------------------------------------
// Fast nonlinearities (MUFU-backed, ~1e-7 rel err)
// ---------------------------------------------------------------------------
__device__ __forceinline__ float sig_f(float x)
{
    return __fdividef(1.f, 1.f + __expf(-x));
}
__device__ __forceinline__ float tanh_f(float x)
{
    return __fdividef(2.f, 1.f + __expf(-2.f * x)) - 1.f;
}

// ---------------------------------------------------------------------------
// Re-sentinel the LSTM output buffers (inside the graph, every replay)
// ---------------------------------------------------------------------------
__global__ void init_sent_kernel()
{
    unsigned idx = blockIdx.x * blockDim.x + threadIdx.x;
    const unsigned total = 2u * T_SEQ * 512u;
    if (idx < total) {
        ((unsigned*)g_h0)[idx] = SENTINEL;
        ((unsigned*)g_h1)[idx] = SENTINEL;
    }
}

// ---------------------------------------------------------------------------
// Layer-0 input gates, 16 timesteps per CTA (weights register-resident).
// grid (4, 128, 4), block 256
// ---------------------------------------------------------------------------
__global__ void __launch_bounds__(256) pre0_kernel(
    const float* __restrict__ v_r, const float* __restrict__ v_l,
    const float* __restrict__ Wih0,
    const float* __restrict__ bih0, const float* __restrict__ bhh0)
{
    const int g     = blockIdx.x * 256 + threadIdx.x;   // 0..1023
    const int tbase = blockIdx.y * 16;
    const int seq   = blockIdx.z;
    const int chain = seq >> 1, dir = seq & 1;

    __shared__ float vs[16][IN_DIM + 2];
    const float* v = (chain ? v_l : v_r) + (size_t)tbase * IN_DIM;
    for (int i = threadIdx.x; i < 16 * IN_DIM; i += 256)
        vs[i / IN_DIM][i % IN_DIM] = v[i];
    __syncthreads();

    float wr[IN_DIM];
    const float* wp = Wih0 + ((size_t)dir * GATES + g) * IN_DIM;
#pragma unroll
    for (int k = 0; k < IN_DIM; k++) wr[k] = __ldg(wp + k);
    const float b = bih0[dir * GATES + g] + bhh0[dir * GATES + g];

    float* outp = g_PRE + ((size_t)seq * T_SEQ + tbase) * GATES + g;
#pragma unroll
    for (int tt = 0; tt < 16; tt++) {
        float s = b;
#pragma unroll
        for (int k = 0; k < IN_DIM; k++) s = fmaf(wr[k], vs[tt][k], s);
        outp[(size_t)tt * GATES] = s;
    }
}

// ---------------------------------------------------------------------------
// Combined layer-1 biases / Ws = W3[:, :H2] + W3[:, H2:]
// ---------------------------------------------------------------------------
__global__ void bsum_kernel(const float* __restrict__ bih1,
                            const float* __restrict__ bhh1)
{
    int i = blockIdx.x * 256 + threadIdx.x;
    if (i < 2 * GATES) g_bs[i] = bih1[i] + bhh1[i];
}

__global__ void ws_kernel(const float* __restrict__ W3)
{
    int idx = blockIdx.x * 256 + threadIdx.x;
    if (idx < D_H3 * D_H2) {
        int i = idx >> 9;
        int j = idx & 511;
        g_Ws[idx] = W3[(size_t)i * (2 * D_H2) + j]
                  + W3[(size_t)i * (2 * D_H2) + D_H2 + j];
    }
}

// ---------------------------------------------------------------------------
// BiLSTM layer. grid = 128 CTAs (4 seqs x 32 chunk-CTAs), block 256, single
// wave. CTA c owns 8 hidden units = 32 gate rows. Warp = unit; lane =
// kq(0..7)*4 + gate(0..3); each thread does 32 MACs over K range
// [kq*32, kq*32+32). Row reduction = 3x shfl_xor(4/8/16); gates of a unit
// land in lanes 0..3 -> 3 index-shfl gather. h_s double-buffered by step
// parity -> exactly ONE __syncthreads per step. Cross-CTA exchange via
// sentinel-polled volatile L2 loads (h in (-1,1), NaN pattern unreachable).
// ---------------------------------------------------------------------------
__global__ void __launch_bounds__(256, 1) lstm_kernel(
    const float* __restrict__ PRE,    // [4][T][1024]
    const float* __restrict__ Whh,    // [2][1024][256]
    float* __restrict__ HB)           // [2][T][512], sentinel-initialized
{
    const int bx    = blockIdx.x;           // 0..127
    const int seq   = bx >> 5;              // 0..3
    const int c     = bx & 31;              // chunk 0..31
    const int chain = seq >> 1, dir = seq & 1;
    const int tid   = threadIdx.x;
    const int u     = tid >> 5;             // unit within chunk = warp id
    const int lane  = tid & 31;
    const int kq    = lane >> 2;            // K eighth 0..7
    const int g     = lane & 3;             // gate (i,f,g,o)
    const int grow  = (g << 8) + (c << 3) + u;   // global gate row

    __shared__ __align__(16) float h_s[2][256];  // [parity][comp]

    // Recurrent weights for this (row, K-eighth) in registers.
    float w[32];
    {
        const float* wp = Whh + ((size_t)dir * GATES + grow) * HID + kq * 32;
#pragma unroll
        for (int i = 0; i < 32; i += 4) {
            float4 v = *(const float4*)(wp + i);
            w[i] = v.x; w[i + 1] = v.y; w[i + 2] = v.z; w[i + 3] = v.w;
        }
    }

    float* hbc = HB + (size_t)chain * T_SEQ * 512;
    const float* prebase = PRE + (size_t)seq * T_SEQ * GATES + grow;

    const int  col = dir * 256 + tid;        // polled h component
    const bool own = ((tid >> 3) == c);      // produced by this CTA
    float cstate = 0.f;                      // valid on lane 0 of each warp

    h_s[0][tid] = 0.f;                       // h_{-1} = 0 (both buffers)
    h_s[1][tid] = 0.f;
    __syncthreads();

    for (int t = 0; t < T_SEQ; t++) {
        const int t_act = dir ? (T_SEQ - 1 - t) : t;
        const int par   = t & 1;

        // Input-gate prefetch (independent of h, overlaps the poll).
        // kq==0 lanes (0..3 of each warp) cover all 32 rows of this CTA.
        float preval = 0.f;
        if (kq == 0)
            preval = __ldg(prebase + (size_t)t_act * GATES);

        if (t > 0 && !own) {
            const int p_act = dir ? (t_act + 1) : (t_act - 1);
            const unsigned* pp =
                (const unsigned*)(hbc + (size_t)p_act * 512 + col);
            unsigned v;
            do {
                asm volatile("ld.volatile.global.u32 %0, [%1];"
                             : "=r"(v) : "l"(pp));
            } while (v == SENTINEL);
            h_s[par][tid] = __uint_as_float(v);
        }
        __syncthreads();

        // 32-MAC partial matvec over smem-broadcast h
        const float* hp = &h_s[par][kq << 5];
        float a0 = 0.f, a1 = 0.f, a2 = 0.f, a3 = 0.f;
#pragma unroll
        for (int i = 0; i < 32; i += 4) {
            float4 hv = *(const float4*)(hp + i);
            a0 = fmaf(w[i],     hv.x, a0);
            a1 = fmaf(w[i + 1], hv.y, a1);
            a2 = fmaf(w[i + 2], hv.z, a2);
            a3 = fmaf(w[i + 3], hv.w, a3);
        }
        float a = (a0 + a1) + (a2 + a3);
        if (kq == 0) a += preval;

        // Sum the 8 K-eighths (kq stride in lane space = 4)
        a += __shfl_xor_sync(0xFFFFFFFFu, a, 4);
        a += __shfl_xor_sync(0xFFFFFFFFu, a, 8);
        a += __shfl_xor_sync(0xFFFFFFFFu, a, 16);
        // Every lane now holds the full row sum for its gate g.

        float gf = __shfl_sync(0xFFFFFFFFu, a, 1, 32);
        float gg = __shfl_sync(0xFFFFFFFFu, a, 2, 32);
        float go = __shfl_sync(0xFFFFFFFFu, a, 3, 32);

        if (lane == 0) {
            float gi = a;
            cstate = sig_f(gf) * cstate + sig_f(gi) * tanh_f(gg);
            float h = sig_f(go) * tanh_f(cstate);
            h_s[par ^ 1][(c << 3) + u] = h;       // next step's buffer
            unsigned hv = __float_as_uint(h);
            unsigned* dst = (unsigned*)(hbc + (size_t)t_act * 512
                                        + dir * 256 + (c << 3) + u);
            asm volatile("st.volatile.global.u32 [%0], %1;" :: "l"(dst), "r"(hv));
        }
    }
}

// ---------------------------------------------------------------------------
// SGEMM: C = act( alpha * ( A[M,K] @ B[N,K]^T + bias[N] ) )
// 128x128 tile, BK=8, 256 threads, 8x8 microtile, register-prefetched K tile.
// Batched via blockIdx.z: A += (z/aDiv)*sA; B += (z%bMod)*sB;
//                         bias += (z%bMod)*sBias; C += z*sC
// ---------------------------------------------------------------------------
__global__ void __launch_bounds__(256) gemm_kernel(
    const float* __restrict__ A, const float* __restrict__ B,
    const float* __restrict__ bias, float* __restrict__ C,
    int M, int N, int K, float alpha, int relu,
    long sA, long sB, long sBias, long sC, int aDiv, int bMod)
{
    A    += (size_t)(blockIdx.z / aDiv) * sA;
    B    += (size_t)(blockIdx.z % bMod) * sB;
    bias += (size_t)(blockIdx.z % bMod) * sBias;
    C    += (size_t)blockIdx.z * sC;

    __shared__ __align__(16) float As[8][132];
    __shared__ __align__(16) float Bs[8][132];

    const int tid = threadIdx.x;
    const int tx = tid & 15, ty = tid >> 4;
    const int m0 = blockIdx.y * 128, n0 = blockIdx.x * 128;
    const int lrow = tid >> 1;
    const int lk   = (tid & 1) << 2;

    float acc[8][8];
#pragma unroll
    for (int i = 0; i < 8; i++)
#pragma unroll
        for (int j = 0; j < 8; j++) acc[i][j] = 0.f;

    const float* Ap = A + (size_t)(m0 + lrow) * K + lk;
    const float* Bp = B + (size_t)(n0 + lrow) * K + lk;

    float4 av = *(const float4*)(Ap);
    float4 bv = *(const float4*)(Bp);

    for (int k0 = 0; k0 < K; k0 += 8) {
        __syncthreads();
        As[lk + 0][lrow] = av.x; As[lk + 1][lrow] = av.y;
        As[lk + 2][lrow] = av.z; As[lk + 3][lrow] = av.w;
        Bs[lk + 0][lrow] = bv.x; Bs[lk + 1][lrow] = bv.y;
        Bs[lk + 2][lrow] = bv.z; Bs[lk + 3][lrow] = bv.w;
        __syncthreads();

        if (k0 + 8 < K) {                    // prefetch next K tile
            av = *(const float4*)(Ap + k0 + 8);
            bv = *(const float4*)(Bp + k0 + 8);
        }

#pragma unroll
        for (int kk = 0; kk < 8; kk++) {
            float4 a0 = *(const float4*)&As[kk][tx << 2];
            float4 a1 = *(const float4*)&As[kk][64 + (tx << 2)];
            float4 b0 = *(const float4*)&Bs[kk][ty << 2];
            float4 b1 = *(const float4*)&Bs[kk][64 + (ty << 2)];
            float ar[8] = {a0.x, a0.y, a0.z, a0.w, a1.x, a1.y, a1.z, a1.w};
            float br[8] = {b0.x, b0.y, b0.z, b0.w, b1.x, b1.y, b1.z, b1.w};
#pragma unroll
            for (int i = 0; i < 8; i++)
#pragma unroll
                for (int j = 0; j < 8; j++)
                    acc[i][j] = fmaf(ar[i], br[j], acc[i][j]);
        }
    }

    float bia[8];
#pragma unroll
    for (int j = 0; j < 8; j++) {
        int n = n0 + ((j < 4) ? (ty << 2) + j : 64 + (ty << 2) + (j - 4));
        bia[j] = bias[n];
    }

#pragma unroll
    for (int i = 0; i < 8; i++) {
        int m = m0 + ((i < 4) ? (tx << 2) + i : 64 + (tx << 2) + (i - 4));
        float v[8];
#pragma unroll
        for (int j = 0; j < 8; j++) {
            float x = alpha * (acc[i][j] + bia[j]);
            v[j] = relu ? fmaxf(x, 0.f) : x;
        }
        float4 o0 = {v[0], v[1], v[2], v[3]};
        float4 o1 = {v[4], v[5], v[6], v[7]};
        *(float4*)(C + (size_t)m * N + n0 + (ty << 2))      = o0;
        *(float4*)(C + (size_t)m * N + n0 + 64 + (ty << 2)) = o1;
    }
}

// ---------------------------------------------------------------------------
// Pair stage: logits[p] = relu(P_r[pr] + P_l[pl]) . Wout^T + bout; log_softmax
// ---------------------------------------------------------------------------
__global__ void __launch_bounds__(256) pair_kernel(
    const int* __restrict__ pair_r, const int* __restrict__ pair_l,
    const float* __restrict__ Wout, const float* __restrict__ bout,
    float* __restrict__ out)
{
    __shared__ float w0[D_H3], w1[D_H3];
    for (int i = threadIdx.x; i < D_H3; i += 256) {
        w0[i] = Wout[i];
        w1[i] = Wout[D_H3 + i];
    }
    __syncthreads();

    const int warp = threadIdx.x >> 5, lane = threadIdx.x & 31;
    const float b0 = bout[0], b1 = bout[1];
    const float* Pr_base = g_P;
    const float* Pl_base = g_P + (size_t)T_SEQ * D_H3;

    for (int p = blockIdx.x * 8 + warp; p < NPAIRS; p += gridDim.x * 8) {
        const float4* Pr = (const float4*)(Pr_base + (size_t)pair_r[p] * D_H3);
        const float4* Pl = (const float4*)(Pl_base + (size_t)pair_l[p] * D_H3);
        float a0 = 0.f, a1 = 0.f;
#pragma unroll 4
        for (int k4 = lane; k4 < D_H3 / 4; k4 += 32) {
            float4 r = __ldg(Pr + k4);
            float4 l = __ldg(Pl + k4);
            int kb = k4 << 2;
            float s0 = fmaxf(r.x + l.x, 0.f);
            float s1 = fmaxf(r.y + l.y, 0.f);
            float s2 = fmaxf(r.z + l.z, 0.f);
            float s3 = fmaxf(r.w + l.w, 0.f);
            a0 = fmaf(s0, w0[kb], a0);     a1 = fmaf(s0, w1[kb], a1);
            a0 = fmaf(s1, w0[kb + 1], a0); a1 = fmaf(s1, w1[kb + 1], a1);
            a0 = fmaf(s2, w0[kb + 2], a0); a1 = fmaf(s2, w1[kb + 2], a1);
            a0 = fmaf(s3, w0[kb + 3], a0); a1 = fmaf(s3, w1[kb + 3], a1);
        }
#pragma unroll
        for (int off = 16; off > 0; off >>= 1) {
            a0 += __shfl_down_sync(0xFFFFFFFFu, a0, off);
            a1 += __shfl_down_sync(0xFFFFFFFFu, a1, off);
        }
        if (lane == 0) {
            float l0 = a0 + b0, l1 = a1 + b1;
            float m = fmaxf(l0, l1);
            float lse = m + logf(expf(l0 - m) + expf(l1 - m));
            out[2 * p]     = l0 - lse;
            out[2 * p + 1] = l1 - lse;
        }
    }
}

// ---------------------------------------------------------------------------
// Host
// ---------------------------------------------------------------------------
extern "C" void kernel_launch(void* const* d_in, const int* in_sizes, int n_in,
                              void* d_out, int out_size)
{
    const float* v_r    = (const float*)d_in[0];
    const float* v_l    = (const float*)d_in[1];
    const int*   pair_r = (const int*)  d_in[2];
    const int*   pair_l = (const int*)  d_in[3];
    const float* Wih0   = (const float*)d_in[4];
    const float* Whh0   = (const float*)d_in[5];
    const float* bih0   = (const float*)d_in[6];
    const float* bhh0   = (const float*)d_in[7];
    const float* Wih1   = (const float*)d_in[8];
    const float* Whh1   = (const float*)d_in[9];
    const float* bih1   = (const float*)d_in[10];
    const float* bhh1   = (const float*)d_in[11];
    const float* W1     = (const float*)d_in[12];
    const float* b1     = (const float*)d_in[13];
    const float* W2     = (const float*)d_in[14];
    const float* b2     = (const float*)d_in[15];
    const float* W3     = (const float*)d_in[16];
    const float* b3     = (const float*)d_in[17];
    const float* Wout   = (const float*)d_in[18];
    const float* bout   = (const float*)d_in[19];
    float* out = (float*)d_out;

    float *PRE, *H0, *H1, *FC1, *ENC, *PT, *WS, *BS;
    cudaGetSymbolAddress((void**)&PRE, g_PRE);
    cudaGetSymbolAddress((void**)&H0,  g_h0);
    cudaGetSymbolAddress((void**)&H1,  g_h1);
    cudaGetSymbolAddress((void**)&FC1, g_fc1);
    cudaGetSymbolAddress((void**)&ENC, g_enc);
    cudaGetSymbolAddress((void**)&PT,  g_P);
    cudaGetSymbolAddress((void**)&WS,  g_Ws);
    cudaGetSymbolAddress((void**)&BS,  g_bs);

    // 1. Sentinel-init LSTM output buffers (every replay)
    init_sent_kernel<<<(2 * T_SEQ * 512 + 255) / 256, 256>>>();

    // 2. Small precomputes
    pre0_kernel<<<dim3(4, 128, 4), 256>>>(v_r, v_l, Wih0, bih0, bhh0);
    bsum_kernel<<<8, 256>>>(bih1, bhh1);
    ws_kernel<<<(D_H3 * D_H2 + 255) / 256, 256>>>(W3);

    // 3. LSTM layer 0 (128 CTAs: 4 seqs x 32 chunks, single wave)
    lstm_kernel<<<128, 256>>>(PRE, Whh0, H0);

    // 4. Layer-1 input gates, batched over seq (z=4):
    //    PRE[seq] = H0[chain] @ Wih1[dir]^T + (bih1+bhh1)[dir]
    gemm_kernel<<<dim3(GATES / 128, T_SEQ / 128, 4), 256>>>(
        H0, Wih1, BS, PRE, T_SEQ, GATES, 512, 1.f, 0,
        (long)T_SEQ * 512, (long)GATES * 512, (long)GATES,
        (long)T_SEQ * GATES, 2, 2);

    // 5. LSTM layer 1
    lstm_kernel<<<128, 256>>>(PRE, Whh1, H1);

    // 6. MLP encoders, batched over chain (z=2)
    gemm_kernel<<<dim3(D_H1 / 128, T_SEQ / 128, 2), 256>>>(
        H1, W1, b1, FC1, T_SEQ, D_H1, 512, 1.f, 1,
        (long)T_SEQ * 512, 0, 0, (long)T_SEQ * D_H1, 1, 1);

    gemm_kernel<<<dim3(D_H2 / 128, T_SEQ / 128, 2), 256>>>(
        FC1, W2, b2, ENC, T_SEQ, D_H2, D_H1, 1.f, 1,
        (long)T_SEQ * D_H1, 0, 0, (long)T_SEQ * D_H2, 1, 1);

    // P = 0.5*(enc @ Ws^T + b3)
    gemm_kernel<<<dim3(D_H3 / 128, T_SEQ / 128, 2), 256>>>(
        ENC, WS, b3, PT, T_SEQ, D_H3, D_H2, 0.5f, 0,
        (long)T_SEQ * D_H2, 0, 0, (long)T_SEQ * D_H3, 1, 1);

    // 7. Pair gather + dot + log_softmax
    pair_kernel<<<2048, 256>>>(pair_r, pair_l, Wout, bout, out);
}

// round 12
// speedup vs baseline: 1.1265x; 1.0944x over previous
#include <cuda_runtime.h>
#include <cuda_bf16.h>
#include <cstdint>
#include <cstddef>
#include <math.h>

// ---------------------------------------------------------------------------
// Problem constants
// ---------------------------------------------------------------------------
#define T_SEQ   2048
#define HID     256
#define GATES   1024      // 4*HID
#define IN_DIM  22
#define D_H1    1024
#define D_H2    512
#define D_H3    1024
#define NPAIRS  65536

#define SENTINEL 0xFFFFFFFFu

// ---------------------------------------------------------------------------
// Scratch (device globals — allocation is forbidden)
// ---------------------------------------------------------------------------
__device__ float g_PRE [4 * T_SEQ * GATES];
__device__ float g_h0  [2 * T_SEQ * 512];
__device__ float g_h1  [2 * T_SEQ * 512];
__device__ float g_fc1 [2 * T_SEQ * D_H1];
__device__ float g_enc [2 * T_SEQ * D_H2];
__device__ float g_P   [2 * T_SEQ * D_H3];
__device__ float g_Ws  [D_H3 * D_H2];
__device__ float g_bs  [2 * GATES];

// ---------------------------------------------------------------------------
// Fast nonlinearities (MUFU-backed, ~1e-7 rel err)
// ---------------------------------------------------------------------------
__device__ __forceinline__ float sig_f(float x)
{
    return __fdividef(1.f, 1.f + __expf(-x));
}
__device__ __forceinline__ float tanh_f(float x)
{
    return __fdividef(2.f, 1.f + __expf(-2.f * x)) - 1.f;
}

// ---------------------------------------------------------------------------
// Re-sentinel the LSTM output buffers (inside the graph, every replay)
// ---------------------------------------------------------------------------
__global__ void init_sent_kernel()
{
    unsigned idx = blockIdx.x * blockDim.x + threadIdx.x;
    const unsigned total = 2u * T_SEQ * 512u;
    if (idx < total) {
        ((unsigned*)g_h0)[idx] = SENTINEL;
        ((unsigned*)g_h1)[idx] = SENTINEL;
    }
}

// ---------------------------------------------------------------------------
// Layer-0 input gates, 16 timesteps per CTA (weights register-resident).
// grid (4, 128, 4), block 256
// ---------------------------------------------------------------------------
__global__ void __launch_bounds__(256) pre0_kernel(
    const float* __restrict__ v_r, const float* __restrict__ v_l,
    const float* __restrict__ Wih0,
    const float* __restrict__ bih0, const float* __restrict__ bhh0)
{
    const int g     = blockIdx.x * 256 + threadIdx.x;   // 0..1023
    const int tbase = blockIdx.y * 16;
    const int seq   = blockIdx.z;
    const int chain = seq >> 1, dir = seq & 1;

    __shared__ float vs[16][IN_DIM + 2];
    const float* v = (chain ? v_l : v_r) + (size_t)tbase * IN_DIM;
    for (int i = threadIdx.x; i < 16 * IN_DIM; i += 256)
        vs[i / IN_DIM][i % IN_DIM] = v[i];
    __syncthreads();

    float wr[IN_DIM];
    const float* wp = Wih0 + ((size_t)dir * GATES + g) * IN_DIM;
#pragma unroll
    for (int k = 0; k < IN_DIM; k++) wr[k] = __ldg(wp + k);
    const float b = bih0[dir * GATES + g] + bhh0[dir * GATES + g];

    float* outp = g_PRE + ((size_t)seq * T_SEQ + tbase) * GATES + g;
#pragma unroll
    for (int tt = 0; tt < 16; tt++) {
        float s = b;
#pragma unroll
        for (int k = 0; k < IN_DIM; k++) s = fmaf(wr[k], vs[tt][k], s);
        outp[(size_t)tt * GATES] = s;
    }
}

// ---------------------------------------------------------------------------
// Combined layer-1 biases / Ws = W3[:, :H2] + W3[:, H2:]
// ---------------------------------------------------------------------------
__global__ void bsum_kernel(const float* __restrict__ bih1,
                            const float* __restrict__ bhh1)
{
    int i = blockIdx.x * 256 + threadIdx.x;
    if (i < 2 * GATES) g_bs[i] = bih1[i] + bhh1[i];
}

__global__ void ws_kernel(const float* __restrict__ W3)
{
    int idx = blockIdx.x * 256 + threadIdx.x;
    if (idx < D_H3 * D_H2) {
        int i = idx >> 9;
        int j = idx & 511;
        g_Ws[idx] = W3[(size_t)i * (2 * D_H2) + j]
                  + W3[(size_t)i * (2 * D_H2) + D_H2 + j];
    }
}

// ---------------------------------------------------------------------------
// BiLSTM layer. grid = 64 CTAs (4 seqs x 16 chunk-CTAs), block 256.
// CTA c owns 16 hidden units = 64 gate rows. Warp w owns units {2w, 2w+1};
// lane = q(2b)*8 + r(3b) with r = gate*2 + unit_lsb; each thread does 64
// MACs over K range [q*64, q*64+64). Row reduction = shfl_xor(8) +
// shfl_xor(16); gate gather = 3 index-shfl (gates of unit ul at lanes
// ul, 2+ul, 4+ul, 6+ul). h_s double-buffered by step parity -> exactly ONE
// __syncthreads per step. Cross-CTA exchange via sentinel-polled volatile
// L2 loads (h in (-1,1) so the NaN bit pattern is unreachable).
// ---------------------------------------------------------------------------
__global__ void __launch_bounds__(256, 1) lstm_kernel(
    const float* __restrict__ PRE,    // [4][T][1024]
    const float* __restrict__ Whh,    // [2][1024][256]
    float* __restrict__ HB)           // [2][T][512], sentinel-initialized
{
    const int bx    = blockIdx.x;           // 0..63
    const int seq   = bx >> 4;              // 0..3
    const int c     = bx & 15;              // chunk 0..15
    const int chain = seq >> 1, dir = seq & 1;
    const int tid   = threadIdx.x;
    const int wrp   = tid >> 5;             // warp 0..7
    const int lane  = tid & 31;
    const int q     = lane >> 3;            // K quarter 0..3
    const int r     = lane & 7;             // row within warp 0..7
    const int g     = r >> 1;               // gate (i,f,g,o)
    const int ul    = r & 1;                // unit lsb
    const int u     = (wrp << 1) + ul;      // unit 0..15
    const int grow  = (g << 8) + (c << 4) + u;   // global gate row

    __shared__ __align__(16) float h_s[2][256];  // [parity][comp]

    // Recurrent weights for this (row, K-quarter) in registers.
    float w[64];
    {
        const float* wp = Whh + ((size_t)dir * GATES + grow) * HID + q * 64;
#pragma unroll
        for (int i = 0; i < 64; i += 4) {
            float4 v = *(const float4*)(wp + i);
            w[i] = v.x; w[i + 1] = v.y; w[i + 2] = v.z; w[i + 3] = v.w;
        }
    }

    float* hbc = HB + (size_t)chain * T_SEQ * 512;
    const float* prebase = PRE + (size_t)seq * T_SEQ * GATES + grow;

    const int  col    = dir * 256 + tid;     // polled h component
    const bool own    = ((tid >> 4) == c);   // produced by this CTA
    const bool isprod = (lane < 2);          // lanes 0,1: units 2w, 2w+1
    float cstate = 0.f;                      // valid on producer lanes

    h_s[0][tid] = 0.f;                       // h_{-1} = 0 (both buffers)
    h_s[1][tid] = 0.f;
    __syncthreads();

    for (int t = 0; t < T_SEQ; t++) {
        const int t_act = dir ? (T_SEQ - 1 - t) : t;
        const int par   = t & 1;

        // Input-gate prefetch (independent of h; q==0 lanes cover all rows)
        float preval = 0.f;
        if (q == 0)
            preval = __ldg(prebase + (size_t)t_act * GATES);

        if (t > 0 && !own) {
            const int p_act = dir ? (t_act + 1) : (t_act - 1);
            const unsigned* pp =
                (const unsigned*)(hbc + (size_t)p_act * 512 + col);
            unsigned v;
            do {
                asm volatile("ld.volatile.global.u32 %0, [%1];"
                             : "=r"(v) : "l"(pp));
            } while (v == SENTINEL);
            h_s[par][tid] = __uint_as_float(v);
        }
        __syncthreads();

        // 64-MAC partial matvec over smem-broadcast h
        const float* hp = &h_s[par][q << 6];
        float a0 = 0.f, a1 = 0.f, a2 = 0.f, a3 = 0.f;
#pragma unroll
        for (int i = 0; i < 64; i += 4) {
            float4 hv = *(const float4*)(hp + i);
            a0 = fmaf(w[i],     hv.x, a0);
            a1 = fmaf(w[i + 1], hv.y, a1);
            a2 = fmaf(w[i + 2], hv.z, a2);
            a3 = fmaf(w[i + 3], hv.w, a3);
        }
        float a = (a0 + a1) + (a2 + a3);
        if (q == 0) a += preval;

        // Sum the 4 K-quarters (q stride in lane space = 8)
        a += __shfl_xor_sync(0xFFFFFFFFu, a, 8);
        a += __shfl_xor_sync(0xFFFFFFFFu, a, 16);
        // Every lane now holds the full row sum for its row r.

        // Gates of unit ul live at lanes ul, 2+ul, 4+ul, 6+ul
        float gf = __shfl_sync(0xFFFFFFFFu, a, 2 + ul, 32);
        float gg = __shfl_sync(0xFFFFFFFFu, a, 4 + ul, 32);
        float go = __shfl_sync(0xFFFFFFFFu, a, 6 + ul, 32);

        if (isprod) {
            float gi = a;                    // lane ul holds gate i of unit u
            cstate = sig_f(gf) * cstate + sig_f(gi) * tanh_f(gg);
            float h = sig_f(go) * tanh_f(cstate);
            h_s[par ^ 1][(c << 4) + u] = h;  // next step's buffer
            unsigned hv = __float_as_uint(h);
            unsigned* dst = (unsigned*)(hbc + (size_t)t_act * 512
                                        + dir * 256 + (c << 4) + u);
            asm volatile("st.volatile.global.u32 [%0], %1;" :: "l"(dst), "r"(hv));
        }
    }
}

// ---------------------------------------------------------------------------
// SGEMM: C = act( alpha * ( A[M,K] @ B[N,K]^T + bias[N] ) )
// 128x128 tile, BK=8, 256 threads, 8x8 microtile (R9 version, no prefetch).
// Batched via blockIdx.z: A += (z/aDiv)*sA; B += (z%bMod)*sB;
//                         bias += (z%bMod)*sBias; C += z*sC
// ---------------------------------------------------------------------------
__global__ void __launch_bounds__(256) gemm_kernel(
    const float* __restrict__ A, const float* __restrict__ B,
    const float* __restrict__ bias, float* __restrict__ C,
    int M, int N, int K, float alpha, int relu,
    long sA, long sB, long sBias, long sC, int aDiv, int bMod)
{
    A    += (size_t)(blockIdx.z / aDiv) * sA;
    B    += (size_t)(blockIdx.z % bMod) * sB;
    bias += (size_t)(blockIdx.z % bMod) * sBias;
    C    += (size_t)blockIdx.z * sC;

    __shared__ __align__(16) float As[8][132];
    __shared__ __align__(16) float Bs[8][132];

    const int tid = threadIdx.x;
    const int tx = tid & 15, ty = tid >> 4;
    const int m0 = blockIdx.y * 128, n0 = blockIdx.x * 128;
    const int lrow = tid >> 1;
    const int lk   = (tid & 1) << 2;

    float acc[8][8];
#pragma unroll
    for (int i = 0; i < 8; i++)
#pragma unroll
        for (int j = 0; j < 8; j++) acc[i][j] = 0.f;

    const float* Ap = A + (size_t)(m0 + lrow) * K + lk;
    const float* Bp = B + (size_t)(n0 + lrow) * K + lk;

    for (int k0 = 0; k0 < K; k0 += 8) {
        float4 av = *(const float4*)(Ap + k0);
        float4 bv = *(const float4*)(Bp + k0);
        __syncthreads();
        As[lk + 0][lrow] = av.x; As[lk + 1][lrow] = av.y;
        As[lk + 2][lrow] = av.z; As[lk + 3][lrow] = av.w;
        Bs[lk + 0][lrow] = bv.x; Bs[lk + 1][lrow] = bv.y;
        Bs[lk + 2][lrow] = bv.z; Bs[lk + 3][lrow] = bv.w;
        __syncthreads();

#pragma unroll
        for (int kk = 0; kk < 8; kk++) {
            float4 a0 = *(const float4*)&As[kk][tx << 2];
            float4 a1 = *(const float4*)&As[kk][64 + (tx << 2)];
            float4 b0 = *(const float4*)&Bs[kk][ty << 2];
            float4 b1 = *(const float4*)&Bs[kk][64 + (ty << 2)];
            float ar[8] = {a0.x, a0.y, a0.z, a0.w, a1.x, a1.y, a1.z, a1.w};
            float br[8] = {b0.x, b0.y, b0.z, b0.w, b1.x, b1.y, b1.z, b1.w};
#pragma unroll
            for (int i = 0; i < 8; i++)
#pragma unroll
                for (int j = 0; j < 8; j++)
                    acc[i][j] = fmaf(ar[i], br[j], acc[i][j]);
        }
    }

    float bia[8];
#pragma unroll
    for (int j = 0; j < 8; j++) {
        int n = n0 + ((j < 4) ? (ty << 2) + j : 64 + (ty << 2) + (j - 4));
        bia[j] = bias[n];
    }

#pragma unroll
    for (int i = 0; i < 8; i++) {
        int m = m0 + ((i < 4) ? (tx << 2) + i : 64 + (tx << 2) + (i - 4));
        float v[8];
#pragma unroll
        for (int j = 0; j < 8; j++) {
            float x = alpha * (acc[i][j] + bia[j]);
            v[j] = relu ? fmaxf(x, 0.f) : x;
        }
        float4 o0 = {v[0], v[1], v[2], v[3]};
        float4 o1 = {v[4], v[5], v[6], v[7]};
        *(float4*)(C + (size_t)m * N + n0 + (ty << 2))      = o0;
        *(float4*)(C + (size_t)m * N + n0 + 64 + (ty << 2)) = o1;
    }
}

// ---------------------------------------------------------------------------
// Pair stage: logits[p] = relu(P_r[pr] + P_l[pl]) . Wout^T + bout; log_softmax
// ---------------------------------------------------------------------------
__global__ void __launch_bounds__(256) pair_kernel(
    const int* __restrict__ pair_r, const int* __restrict__ pair_l,
    const float* __restrict__ Wout, const float* __restrict__ bout,
    float* __restrict__ out)
{
    __shared__ float w0[D_H3], w1[D_H3];
    for (int i = threadIdx.x; i < D_H3; i += 256) {
        w0[i] = Wout[i];
        w1[i] = Wout[D_H3 + i];
    }
    __syncthreads();

    const int warp = threadIdx.x >> 5, lane = threadIdx.x & 31;
    const float b0 = bout[0], b1 = bout[1];
    const float* Pr_base = g_P;
    const float* Pl_base = g_P + (size_t)T_SEQ * D_H3;

    for (int p = blockIdx.x * 8 + warp; p < NPAIRS; p += gridDim.x * 8) {
        const float4* Pr = (const float4*)(Pr_base + (size_t)pair_r[p] * D_H3);
        const float4* Pl = (const float4*)(Pl_base + (size_t)pair_l[p] * D_H3);
        float a0 = 0.f, a1 = 0.f;
#pragma unroll 4
        for (int k4 = lane; k4 < D_H3 / 4; k4 += 32) {
            float4 r = __ldg(Pr + k4);
            float4 l = __ldg(Pl + k4);
            int kb = k4 << 2;
            float s0 = fmaxf(r.x + l.x, 0.f);
            float s1 = fmaxf(r.y + l.y, 0.f);
            float s2 = fmaxf(r.z + l.z, 0.f);
            float s3 = fmaxf(r.w + l.w, 0.f);
            a0 = fmaf(s0, w0[kb], a0);     a1 = fmaf(s0, w1[kb], a1);
            a0 = fmaf(s1, w0[kb + 1], a0); a1 = fmaf(s1, w1[kb + 1], a1);
            a0 = fmaf(s2, w0[kb + 2], a0); a1 = fmaf(s2, w1[kb + 2], a1);
            a0 = fmaf(s3, w0[kb + 3], a0); a1 = fmaf(s3, w1[kb + 3], a1);
        }
#pragma unroll
        for (int off = 16; off > 0; off >>= 1) {
            a0 += __shfl_down_sync(0xFFFFFFFFu, a0, off);
            a1 += __shfl_down_sync(0xFFFFFFFFu, a1, off);
        }
        if (lane == 0) {
            float l0 = a0 + b0, l1 = a1 + b1;
            float m = fmaxf(l0, l1);
            float lse = m + logf(expf(l0 - m) + expf(l1 - m));
            out[2 * p]     = l0 - lse;
            out[2 * p + 1] = l1 - lse;
        }
    }
}

// ---------------------------------------------------------------------------
// Host — launch order arranged so the ncu profiled slot lands on lstm_kernel
// ---------------------------------------------------------------------------
extern "C" void kernel_launch(void* const* d_in, const int* in_sizes, int n_in,
                              void* d_out, int out_size)
{
    const float* v_r    = (const float*)d_in[0];
    const float* v_l    = (const float*)d_in[1];
    const int*   pair_r = (const int*)  d_in[2];
    const int*   pair_l = (const int*)  d_in[3];
    const float* Wih0   = (const float*)d_in[4];
    const float* Whh0   = (const float*)d_in[5];
    const float* bih0   = (const float*)d_in[6];
    const float* bhh0   = (const float*)d_in[7];
    const float* Wih1   = (const float*)d_in[8];
    const float* Whh1   = (const float*)d_in[9];
    const float* bih1   = (const float*)d_in[10];
    const float* bhh1   = (const float*)d_in[11];
    const float* W1     = (const float*)d_in[12];
    const float* b1     = (const float*)d_in[13];
    const float* W2     = (const float*)d_in[14];
    const float* b2     = (const float*)d_in[15];
    const float* W3     = (const float*)d_in[16];
    const float* b3     = (const float*)d_in[17];
    const float* Wout   = (const float*)d_in[18];
    const float* bout   = (const float*)d_in[19];
    float* out = (float*)d_out;

    float *PRE, *H0, *H1, *FC1, *ENC, *PT, *WS, *BS;
    cudaGetSymbolAddress((void**)&PRE, g_PRE);
    cudaGetSymbolAddress((void**)&H0,  g_h0);
    cudaGetSymbolAddress((void**)&H1,  g_h1);
    cudaGetSymbolAddress((void**)&FC1, g_fc1);
    cudaGetSymbolAddress((void**)&ENC, g_enc);
    cudaGetSymbolAddress((void**)&PT,  g_P);
    cudaGetSymbolAddress((void**)&WS,  g_Ws);
    cudaGetSymbolAddress((void**)&BS,  g_bs);

    // 1. Sentinel-init LSTM output buffers (every replay)
    init_sent_kernel<<<(2 * T_SEQ * 512 + 255) / 256, 256>>>();

    // 2. Precomputes needed before lstm0 / gemm(step 4)
    pre0_kernel<<<dim3(4, 128, 4), 256>>>(v_r, v_l, Wih0, bih0, bhh0);
    bsum_kernel<<<8, 256>>>(bih1, bhh1);

    // 3. LSTM layer 0 (64 CTAs: 4 seqs x 16 chunks)
    lstm_kernel<<<64, 256>>>(PRE, Whh0, H0);

    // 4. Layer-1 input gates, batched over seq (z=4):
    //    PRE[seq] = H0[chain] @ Wih1[dir]^T + (bih1+bhh1)[dir]
    gemm_kernel<<<dim3(GATES / 128, T_SEQ / 128, 4), 256>>>(
        H0, Wih1, BS, PRE, T_SEQ, GATES, 512, 1.f, 0,
        (long)T_SEQ * 512, (long)GATES * 512, (long)GATES,
        (long)T_SEQ * GATES, 2, 2);

    // 5. LSTM layer 1
    lstm_kernel<<<64, 256>>>(PRE, Whh1, H1);

    // 6. MLP encoders, batched over chain (z=2)
    gemm_kernel<<<dim3(D_H1 / 128, T_SEQ / 128, 2), 256>>>(
        H1, W1, b1, FC1, T_SEQ, D_H1, 512, 1.f, 1,
        (long)T_SEQ * 512, 0, 0, (long)T_SEQ * D_H1, 1, 1);

    gemm_kernel<<<dim3(D_H2 / 128, T_SEQ / 128, 2), 256>>>(
        FC1, W2, b2, ENC, T_SEQ, D_H2, D_H1, 1.f, 1,
        (long)T_SEQ * D_H1, 0, 0, (long)T_SEQ * D_H2, 1, 1);

    // Ws fold (only needed before the P projection)
    ws_kernel<<<(D_H3 * D_H2 + 255) / 256, 256>>>(W3);

    // P = 0.5*(enc @ Ws^T + b3)
    gemm_kernel<<<dim3(D_H3 / 128, T_SEQ / 128, 2), 256>>>(
        ENC, WS, b3, PT, T_SEQ, D_H3, D_H2, 0.5f, 0,
        (long)T_SEQ * D_H2, 0, 0, (long)T_SEQ * D_H3, 1, 1);

    // 7. Pair gather + dot + log_softmax
    pair_kernel<<<2048, 256>>>(pair_r, pair_l, Wout, bout, out);
}

// round 13
// speedup vs baseline: 1.6291x; 1.4462x over previous
#include <cuda_runtime.h>
#include <cuda_bf16.h>
#include <cstdint>
#include <cstddef>
#include <math.h>

// ---------------------------------------------------------------------------
// Problem constants
// ---------------------------------------------------------------------------
#define T_SEQ   2048
#define HID     256
#define GATES   1024      // 4*HID
#define IN_DIM  22
#define D_H1    1024
#define D_H2    512
#define D_H3    1024
#define NPAIRS  65536

#define SENTINEL 0xFFFFFFFFu

// ---------------------------------------------------------------------------
// Scratch (device globals — allocation is forbidden)
// ---------------------------------------------------------------------------
__device__ float g_PRE [4 * T_SEQ * GATES];
__device__ float g_h0  [2 * T_SEQ * 512];
__device__ float g_h1  [2 * T_SEQ * 512];
__device__ float g_fc1 [2 * T_SEQ * D_H1];
__device__ float g_enc [2 * T_SEQ * D_H2];
__device__ float g_P   [2 * T_SEQ * D_H3];
__device__ float g_Ws  [D_H3 * D_H2];
__device__ float g_bs  [2 * GATES];

// ---------------------------------------------------------------------------
// Fast nonlinearities (MUFU-backed, ~1e-7 rel err)
// ---------------------------------------------------------------------------
__device__ __forceinline__ float sig_f(float x)
{
    return __fdividef(1.f, 1.f + __expf(-x));
}
__device__ __forceinline__ float tanh_f(float x)
{
    return __fdividef(2.f, 1.f + __expf(-2.f * x)) - 1.f;
}

// ---------------------------------------------------------------------------
// Re-sentinel LSTM output buffers (fallback path only)
// ---------------------------------------------------------------------------
__global__ void init_sent_kernel()
{
    unsigned idx = blockIdx.x * blockDim.x + threadIdx.x;
    const unsigned total = 2u * T_SEQ * 512u;
    if (idx < total) {
        ((unsigned*)g_h0)[idx] = SENTINEL;
        ((unsigned*)g_h1)[idx] = SENTINEL;
    }
}

// ---------------------------------------------------------------------------
// Layer-0 input gates, 16 timesteps per CTA (weights register-resident).
// grid (4, 128, 4), block 256
// ---------------------------------------------------------------------------
__global__ void __launch_bounds__(256) pre0_kernel(
    const float* __restrict__ v_r, const float* __restrict__ v_l,
    const float* __restrict__ Wih0,
    const float* __restrict__ bih0, const float* __restrict__ bhh0)
{
    const int g     = blockIdx.x * 256 + threadIdx.x;   // 0..1023
    const int tbase = blockIdx.y * 16;
    const int seq   = blockIdx.z;
    const int chain = seq >> 1, dir = seq & 1;

    __shared__ float vs[16][IN_DIM + 2];
    const float* v = (chain ? v_l : v_r) + (size_t)tbase * IN_DIM;
    for (int i = threadIdx.x; i < 16 * IN_DIM; i += 256)
        vs[i / IN_DIM][i % IN_DIM] = v[i];
    __syncthreads();

    float wr[IN_DIM];
    const float* wp = Wih0 + ((size_t)dir * GATES + g) * IN_DIM;
#pragma unroll
    for (int k = 0; k < IN_DIM; k++) wr[k] = __ldg(wp + k);
    const float b = bih0[dir * GATES + g] + bhh0[dir * GATES + g];

    float* outp = g_PRE + ((size_t)seq * T_SEQ + tbase) * GATES + g;
#pragma unroll
    for (int tt = 0; tt < 16; tt++) {
        float s = b;
#pragma unroll
        for (int k = 0; k < IN_DIM; k++) s = fmaf(wr[k], vs[tt][k], s);
        outp[(size_t)tt * GATES] = s;
    }
}

// ---------------------------------------------------------------------------
// Combined layer-1 biases / Ws = W3[:, :H2] + W3[:, H2:]
// ---------------------------------------------------------------------------
__global__ void bsum_kernel(const float* __restrict__ bih1,
                            const float* __restrict__ bhh1)
{
    int i = blockIdx.x * 256 + threadIdx.x;
    if (i < 2 * GATES) g_bs[i] = bih1[i] + bhh1[i];
}

__global__ void ws_kernel(const float* __restrict__ W3)
{
    int idx = blockIdx.x * 256 + threadIdx.x;
    if (idx < D_H3 * D_H2) {
        int i = idx >> 9;
        int j = idx & 511;
        g_Ws[idx] = W3[(size_t)i * (2 * D_H2) + j]
                  + W3[(size_t)i * (2 * D_H2) + D_H2 + j];
    }
}

// ---------------------------------------------------------------------------
// CLUSTER BiLSTM layer. grid = 64 CTAs, clusterDim = 16 (one cluster per
// sequence). CTA c owns 16 hidden units = 64 gate rows; thread layout and
// reduction IDENTICAL to the proven R9 kernel (rloc = tid&63, kq = tid>>6,
// part[] smem reduction, 3 barriers/step). Transport: producers PUSH h into
// all 15 peers' smem mailboxes via mapa + st.shared::cluster; consumers
// poll LOCAL smem (ld.volatile.shared) and self-reset the slot. h in (-1,1)
// so the SENTINEL (NaN) pattern is unreachable.
// ---------------------------------------------------------------------------
__global__ void __launch_bounds__(256, 1) lstm_cluster_kernel(
    const float* __restrict__ PRE,    // [4][T][1024]
    const float* __restrict__ Whh,    // [2][1024][256]
    float* __restrict__ HB)           // [2][T][512]
{
    const int bx    = blockIdx.x;           // 0..63
    const int seq   = bx >> 4;              // 0..3  (cluster id)
    const int c     = bx & 15;              // chunk = cluster rank
    const int chain = seq >> 1, dir = seq & 1;
    const int tid   = threadIdx.x;
    const int rloc  = tid & 63;             // local gate row
    const int kq    = tid >> 6;             // K quarter 0..3
    const int gidx  = rloc >> 4;            // gate (i,f,g,o)
    const int jl    = rloc & 15;            // unit within chunk
    const int grow  = (gidx << 8) + (c << 4) + jl;   // global gate row

    __shared__ __align__(16) float h_s[2][256];
    __shared__ unsigned mbox[2][256];       // mailbox, sentinel protocol
    __shared__ float part[256];
    __shared__ float gate_s[64];

    // Recurrent weights for this (row, K-quarter) in registers.
    float w[64];
    {
        const float* wp = Whh + ((size_t)dir * GATES + grow) * HID + kq * 64;
#pragma unroll
        for (int i = 0; i < 64; i += 4) {
            float4 v = *(const float4*)(wp + i);
            w[i] = v.x; w[i + 1] = v.y; w[i + 2] = v.z; w[i + 3] = v.w;
        }
    }

    float* hbc = HB + (size_t)chain * T_SEQ * 512;
    const float* prebase = PRE + (size_t)seq * T_SEQ * GATES + grow;

    const bool own    = ((tid >> 4) == c);   // comp tid produced locally
    const bool isprod = (tid < 16);          // producer: unit u = tid
    float cstate = 0.f;

    const uint32_t mbox_u32 = (uint32_t)__cvta_generic_to_shared(&mbox[0][0]);
    const uint32_t mypoll   = mbox_u32 + (tid << 2);   // mbox[0][tid]

    // Precompute peer mailbox addresses for this producer's component.
    uint32_t peerAddr[15];
    if (isprod) {
        uint32_t myaddr = mbox_u32 + (((c << 4) + tid) << 2);
#pragma unroll
        for (int p = 0; p < 15; p++) {
            int rank = p + (p >= c ? 1 : 0);
            asm("mapa.shared::cluster.u32 %0, %1, %2;"
                : "=r"(peerAddr[p]) : "r"(myaddr), "r"(rank));
        }
    }

    h_s[0][tid] = 0.f;                      // h_{-1} = 0
    h_s[1][tid] = 0.f;
    mbox[0][tid] = SENTINEL;
    mbox[1][tid] = SENTINEL;
    __syncthreads();
    asm volatile("barrier.cluster.arrive.aligned;" ::: "memory");
    asm volatile("barrier.cluster.wait.aligned;" ::: "memory");

    for (int t = 0; t < T_SEQ; t++) {
        const int t_act = dir ? (T_SEQ - 1 - t) : t;
        const int par   = t & 1;

        // Input-gate prefetch (independent of h, overlaps the poll)
        float preval = 0.f;
        if (tid < 64)
            preval = __ldg(prebase + (size_t)t_act * GATES);

        if (t > 0 && !own) {
            const uint32_t a = mypoll + (par << 10);
            unsigned v;
            do {
                asm volatile("ld.volatile.shared.u32 %0, [%1];"
                             : "=r"(v) : "r"(a));
            } while (v == SENTINEL);
            asm volatile("st.shared.u32 [%0], %1;" :: "r"(a), "r"(SENTINEL));
            h_s[par][tid] = __uint_as_float(v);
        }
        __syncthreads();

        // 64-MAC partial matvec over smem-broadcast h
        const float* hp = &h_s[par][kq << 6];
        float a0 = 0.f, a1 = 0.f, a2 = 0.f, a3 = 0.f;
#pragma unroll
        for (int i = 0; i < 64; i += 4) {
            float4 hv = *(const float4*)(hp + i);
            a0 = fmaf(w[i],     hv.x, a0);
            a1 = fmaf(w[i + 1], hv.y, a1);
            a2 = fmaf(w[i + 2], hv.z, a2);
            a3 = fmaf(w[i + 3], hv.w, a3);
        }
        part[tid] = (a0 + a1) + (a2 + a3);
        __syncthreads();

        if (tid < 64)
            gate_s[tid] = preval + part[tid] + part[tid + 64]
                        + part[tid + 128] + part[tid + 192];
        __syncthreads();

        if (isprod) {
            float gi = gate_s[tid];          // gate order i,f,g,o
            float gf = gate_s[16 + tid];
            float gg = gate_s[32 + tid];
            float go = gate_s[48 + tid];
            cstate = sig_f(gf) * cstate + sig_f(gi) * tanh_f(gg);
            float h = sig_f(go) * tanh_f(cstate);
            h_s[par ^ 1][(c << 4) + tid] = h;          // own comp, next step
            hbc[(size_t)t_act * 512 + dir * 256 + (c << 4) + tid] = h;
            if (t < T_SEQ - 1) {
                unsigned hv = __float_as_uint(h);
                const uint32_t off = (unsigned)(par ^ 1) << 10;
#pragma unroll
                for (int p = 0; p < 15; p++)
                    asm volatile("st.shared::cluster.u32 [%0], %1;"
                                 :: "r"(peerAddr[p] + off), "r"(hv));
            }
        }
    }
}

// ---------------------------------------------------------------------------
// FALLBACK BiLSTM layer (R9 exact): L2 sentinel polling, grid 64, block 256.
// ---------------------------------------------------------------------------
__global__ void __launch_bounds__(256, 1) lstm_kernel(
    const float* __restrict__ PRE,
    const float* __restrict__ Whh,
    float* __restrict__ HB)           // sentinel-initialized
{
    const int bx    = blockIdx.x;
    const int seq   = bx >> 4;
    const int c     = bx & 15;
    const int chain = seq >> 1, dir = seq & 1;
    const int tid   = threadIdx.x;
    const int rloc  = tid & 63;
    const int kq    = tid >> 6;
    const int gidx  = rloc >> 4;
    const int jl    = rloc & 15;
    const int grow  = (gidx << 8) + (c << 4) + jl;

    __shared__ __align__(16) float h_s[256];
    __shared__ float part[256];
    __shared__ float gate_s[64];

    float w[64];
    {
        const float* wp = Whh + ((size_t)dir * GATES + grow) * HID + kq * 64;
#pragma unroll
        for (int i = 0; i < 64; i += 4) {
            float4 v = *(const float4*)(wp + i);
            w[i] = v.x; w[i + 1] = v.y; w[i + 2] = v.z; w[i + 3] = v.w;
        }
    }

    float* hbc = HB + (size_t)chain * T_SEQ * 512;
    const float* prebase = PRE + (size_t)seq * T_SEQ * GATES + grow;
    const int  col = dir * 256 + tid;
    const bool own = ((tid >> 4) == c);
    float cstate = 0.f;

    h_s[tid] = 0.f;
    __syncthreads();

    for (int t = 0; t < T_SEQ; t++) {
        const int t_act = dir ? (T_SEQ - 1 - t) : t;

        float preval = 0.f;
        if (tid < 64)
            preval = __ldg(prebase + (size_t)t_act * GATES);

        if (t > 0 && !own) {
            const int p_act = dir ? (t_act + 1) : (t_act - 1);
            const unsigned* pp =
                (const unsigned*)(hbc + (size_t)p_act * 512 + col);
            unsigned v;
            do {
                asm volatile("ld.volatile.global.u32 %0, [%1];"
                             : "=r"(v) : "l"(pp));
            } while (v == SENTINEL);
            h_s[tid] = __uint_as_float(v);
        }
        __syncthreads();

        const float* hp = h_s + (kq << 6);
        float a0 = 0.f, a1 = 0.f, a2 = 0.f, a3 = 0.f;
#pragma unroll
        for (int i = 0; i < 64; i += 4) {
            float4 hv = *(const float4*)(hp + i);
            a0 = fmaf(w[i],     hv.x, a0);
            a1 = fmaf(w[i + 1], hv.y, a1);
            a2 = fmaf(w[i + 2], hv.z, a2);
            a3 = fmaf(w[i + 3], hv.w, a3);
        }
        part[tid] = (a0 + a1) + (a2 + a3);
        __syncthreads();

        if (tid < 64)
            gate_s[tid] = preval + part[tid] + part[tid + 64]
                        + part[tid + 128] + part[tid + 192];
        __syncthreads();

        if (tid < 16) {
            float gi = gate_s[tid];
            float gf = gate_s[16 + tid];
            float gg = gate_s[32 + tid];
            float go = gate_s[48 + tid];
            cstate = sig_f(gf) * cstate + sig_f(gi) * tanh_f(gg);
            float h = sig_f(go) * tanh_f(cstate);
            h_s[(c << 4) + tid] = h;
            unsigned hv = __float_as_uint(h);
            unsigned* dst = (unsigned*)(hbc + (size_t)t_act * 512
                                        + dir * 256 + (c << 4) + tid);
            asm volatile("st.volatile.global.u32 [%0], %1;" :: "l"(dst), "r"(hv));
        }
        __syncthreads();
    }
}

// ---------------------------------------------------------------------------
// SGEMM: C = act( alpha * ( A[M,K] @ B[N,K]^T + bias[N] ) )
// 128x128 tile, BK=8, 256 threads, 8x8 microtile (R9 version).
// ---------------------------------------------------------------------------
__global__ void __launch_bounds__(256) gemm_kernel(
    const float* __restrict__ A, const float* __restrict__ B,
    const float* __restrict__ bias, float* __restrict__ C,
    int M, int N, int K, float alpha, int relu,
    long sA, long sB, long sBias, long sC, int aDiv, int bMod)
{
    A    += (size_t)(blockIdx.z / aDiv) * sA;
    B    += (size_t)(blockIdx.z % bMod) * sB;
    bias += (size_t)(blockIdx.z % bMod) * sBias;
    C    += (size_t)blockIdx.z * sC;

    __shared__ __align__(16) float As[8][132];
    __shared__ __align__(16) float Bs[8][132];

    const int tid = threadIdx.x;
    const int tx = tid & 15, ty = tid >> 4;
    const int m0 = blockIdx.y * 128, n0 = blockIdx.x * 128;
    const int lrow = tid >> 1;
    const int lk   = (tid & 1) << 2;

    float acc[8][8];
#pragma unroll
    for (int i = 0; i < 8; i++)
#pragma unroll
        for (int j = 0; j < 8; j++) acc[i][j] = 0.f;

    const float* Ap = A + (size_t)(m0 + lrow) * K + lk;
    const float* Bp = B + (size_t)(n0 + lrow) * K + lk;

    for (int k0 = 0; k0 < K; k0 += 8) {
        float4 av = *(const float4*)(Ap + k0);
        float4 bv = *(const float4*)(Bp + k0);
        __syncthreads();
        As[lk + 0][lrow] = av.x; As[lk + 1][lrow] = av.y;
        As[lk + 2][lrow] = av.z; As[lk + 3][lrow] = av.w;
        Bs[lk + 0][lrow] = bv.x; Bs[lk + 1][lrow] = bv.y;
        Bs[lk + 2][lrow] = bv.z; Bs[lk + 3][lrow] = bv.w;
        __syncthreads();

#pragma unroll
        for (int kk = 0; kk < 8; kk++) {
            float4 a0 = *(const float4*)&As[kk][tx << 2];
            float4 a1 = *(const float4*)&As[kk][64 + (tx << 2)];
            float4 b0 = *(const float4*)&Bs[kk][ty << 2];
            float4 b1 = *(const float4*)&Bs[kk][64 + (ty << 2)];
            float ar[8] = {a0.x, a0.y, a0.z, a0.w, a1.x, a1.y, a1.z, a1.w};
            float br[8] = {b0.x, b0.y, b0.z, b0.w, b1.x, b1.y, b1.z, b1.w};
#pragma unroll
            for (int i = 0; i < 8; i++)
#pragma unroll
                for (int j = 0; j < 8; j++)
                    acc[i][j] = fmaf(ar[i], br[j], acc[i][j]);
        }
    }

    float bia[8];
#pragma unroll
    for (int j = 0; j < 8; j++) {
        int n = n0 + ((j < 4) ? (ty << 2) + j : 64 + (ty << 2) + (j - 4));
        bia[j] = bias[n];
    }

#pragma unroll
    for (int i = 0; i < 8; i++) {
        int m = m0 + ((i < 4) ? (tx << 2) + i : 64 + (tx << 2) + (i - 4));
        float v[8];
#pragma unroll
        for (int j = 0; j < 8; j++) {
            float x = alpha * (acc[i][j] + bia[j]);
            v[j] = relu ? fmaxf(x, 0.f) : x;
        }
        float4 o0 = {v[0], v[1], v[2], v[3]};
        float4 o1 = {v[4], v[5], v[6], v[7]};
        *(float4*)(C + (size_t)m * N + n0 + (ty << 2))      = o0;
        *(float4*)(C + (size_t)m * N + n0 + 64 + (ty << 2)) = o1;
    }
}

// ---------------------------------------------------------------------------
// Pair stage: logits[p] = relu(P_r[pr] + P_l[pl]) . Wout^T + bout; log_softmax
// ---------------------------------------------------------------------------
__global__ void __launch_bounds__(256) pair_kernel(
    const int* __restrict__ pair_r, const int* __restrict__ pair_l,
    const float* __restrict__ Wout, const float* __restrict__ bout,
    float* __restrict__ out)
{
    __shared__ float w0[D_H3], w1[D_H3];
    for (int i = threadIdx.x; i < D_H3; i += 256) {
        w0[i] = Wout[i];
        w1[i] = Wout[D_H3 + i];
    }
    __syncthreads();

    const int warp = threadIdx.x >> 5, lane = threadIdx.x & 31;
    const float b0 = bout[0], b1 = bout[1];
    const float* Pr_base = g_P;
    const float* Pl_base = g_P + (size_t)T_SEQ * D_H3;

    for (int p = blockIdx.x * 8 + warp; p < NPAIRS; p += gridDim.x * 8) {
        const float4* Pr = (const float4*)(Pr_base + (size_t)pair_r[p] * D_H3);
        const float4* Pl = (const float4*)(Pl_base + (size_t)pair_l[p] * D_H3);
        float a0 = 0.f, a1 = 0.f;
#pragma unroll 4
        for (int k4 = lane; k4 < D_H3 / 4; k4 += 32) {
            float4 r = __ldg(Pr + k4);
            float4 l = __ldg(Pl + k4);
            int kb = k4 << 2;
            float s0 = fmaxf(r.x + l.x, 0.f);
            float s1 = fmaxf(r.y + l.y, 0.f);
            float s2 = fmaxf(r.z + l.z, 0.f);
            float s3 = fmaxf(r.w + l.w, 0.f);
            a0 = fmaf(s0, w0[kb], a0);     a1 = fmaf(s0, w1[kb], a1);
            a0 = fmaf(s1, w0[kb + 1], a0); a1 = fmaf(s1, w1[kb + 1], a1);
            a0 = fmaf(s2, w0[kb + 2], a0); a1 = fmaf(s2, w1[kb + 2], a1);
            a0 = fmaf(s3, w0[kb + 3], a0); a1 = fmaf(s3, w1[kb + 3], a1);
        }
#pragma unroll
        for (int off = 16; off > 0; off >>= 1) {
            a0 += __shfl_down_sync(0xFFFFFFFFu, a0, off);
            a1 += __shfl_down_sync(0xFFFFFFFFu, a1, off);
        }
        if (lane == 0) {
            float l0 = a0 + b0, l1 = a1 + b1;
            float m = fmaxf(l0, l1);
            float lse = m + logf(expf(l0 - m) + expf(l1 - m));
            out[2 * p]     = l0 - lse;
            out[2 * p + 1] = l1 - lse;
        }
    }
}

// ---------------------------------------------------------------------------
// Host
// ---------------------------------------------------------------------------
extern "C" void kernel_launch(void* const* d_in, const int* in_sizes, int n_in,
                              void* d_out, int out_size)
{
    const float* v_r    = (const float*)d_in[0];
    const float* v_l    = (const float*)d_in[1];
    const int*   pair_r = (const int*)  d_in[2];
    const int*   pair_l = (const int*)  d_in[3];
    const float* Wih0   = (const float*)d_in[4];
    const float* Whh0   = (const float*)d_in[5];
    const float* bih0   = (const float*)d_in[6];
    const float* bhh0   = (const float*)d_in[7];
    const float* Wih1   = (const float*)d_in[8];
    const float* Whh1   = (const float*)d_in[9];
    const float* bih1   = (const float*)d_in[10];
    const float* bhh1   = (const float*)d_in[11];
    const float* W1     = (const float*)d_in[12];
    const float* b1     = (const float*)d_in[13];
    const float* W2     = (const float*)d_in[14];
    const float* b2     = (const float*)d_in[15];
    const float* W3     = (const float*)d_in[16];
    const float* b3     = (const float*)d_in[17];
    const float* Wout   = (const float*)d_in[18];
    const float* bout   = (const float*)d_in[19];
    float* out = (float*)d_out;

    float *PRE, *H0, *H1, *FC1, *ENC, *PT, *WS, *BS;
    cudaGetSymbolAddress((void**)&PRE, g_PRE);
    cudaGetSymbolAddress((void**)&H0,  g_h0);
    cudaGetSymbolAddress((void**)&H1,  g_h1);
    cudaGetSymbolAddress((void**)&FC1, g_fc1);
    cudaGetSymbolAddress((void**)&ENC, g_enc);
    cudaGetSymbolAddress((void**)&PT,  g_P);
    cudaGetSymbolAddress((void**)&WS,  g_Ws);
    cudaGetSymbolAddress((void**)&BS,  g_bs);

    // --- Probe cluster-16 support (pure host query, capture-safe) ---
    cudaFuncSetAttribute(lstm_cluster_kernel,
                         cudaFuncAttributeNonPortableClusterSizeAllowed, 1);
    cudaLaunchConfig_t cfg = {};
    cfg.gridDim  = dim3(64, 1, 1);
    cfg.blockDim = dim3(256, 1, 1);
    cudaLaunchAttribute attrs[1];
    attrs[0].id = cudaLaunchAttributeClusterDimension;
    attrs[0].val.clusterDim = {16, 1, 1};
    cfg.attrs = attrs;
    cfg.numAttrs = 1;
    int numClusters = 0;
    cudaError_t qe = cudaOccupancyMaxActiveClusters(
        &numClusters, lstm_cluster_kernel, &cfg);
    bool use_cluster = (qe == cudaSuccess && numClusters >= 4);
    if (!use_cluster) cudaGetLastError();   // clear sticky error

    // 1. Precomputes
    pre0_kernel<<<dim3(4, 128, 4), 256>>>(v_r, v_l, Wih0, bih0, bhh0);
    bsum_kernel<<<8, 256>>>(bih1, bhh1);

    // 2. LSTM layer 0
    if (use_cluster) {
        cudaLaunchKernelEx(&cfg, lstm_cluster_kernel,
                           (const float*)PRE, Whh0, H0);
    } else {
        init_sent_kernel<<<(2 * T_SEQ * 512 + 255) / 256, 256>>>();
        lstm_kernel<<<64, 256>>>(PRE, Whh0, H0);
    }

    // 3. Layer-1 input gates, batched over seq (z=4)
    gemm_kernel<<<dim3(GATES / 128, T_SEQ / 128, 4), 256>>>(
        H0, Wih1, BS, PRE, T_SEQ, GATES, 512, 1.f, 0,
        (long)T_SEQ * 512, (long)GATES * 512, (long)GATES,
        (long)T_SEQ * GATES, 2, 2);

    // 4. LSTM layer 1
    if (use_cluster) {
        cudaLaunchKernelEx(&cfg, lstm_cluster_kernel,
                           (const float*)PRE, Whh1, H1);
    } else {
        lstm_kernel<<<64, 256>>>(PRE, Whh1, H1);
    }

    // 5. MLP encoders, batched over chain (z=2)
    gemm_kernel<<<dim3(D_H1 / 128, T_SEQ / 128, 2), 256>>>(
        H1, W1, b1, FC1, T_SEQ, D_H1, 512, 1.f, 1,
        (long)T_SEQ * 512, 0, 0, (long)T_SEQ * D_H1, 1, 1);

    gemm_kernel<<<dim3(D_H2 / 128, T_SEQ / 128, 2), 256>>>(
        FC1, W2, b2, ENC, T_SEQ, D_H2, D_H1, 1.f, 1,
        (long)T_SEQ * D_H1, 0, 0, (long)T_SEQ * D_H2, 1, 1);

    ws_kernel<<<(D_H3 * D_H2 + 255) / 256, 256>>>(W3);

    // P = 0.5*(enc @ Ws^T + b3)
    gemm_kernel<<<dim3(D_H3 / 128, T_SEQ / 128, 2), 256>>>(
        ENC, WS, b3, PT, T_SEQ, D_H3, D_H2, 0.5f, 0,
        (long)T_SEQ * D_H2, 0, 0, (long)T_SEQ * D_H3, 1, 1);

    // 6. Pair gather + dot + log_softmax
    pair_kernel<<<2048, 256>>>(pair_r, pair_l, Wout, bout, out);
}

// round 14
// speedup vs baseline: 1.7046x; 1.0463x over previous
#include <cuda_runtime.h>
#include <cuda_bf16.h>
#include <cstdint>
#include <cstddef>
#include <math.h>

// ---------------------------------------------------------------------------
// Problem constants
// ---------------------------------------------------------------------------
#define T_SEQ   2048
#define HID     256
#define GATES   1024      // 4*HID
#define IN_DIM  22
#define D_H1    1024
#define D_H2    512
#define D_H3    1024
#define NPAIRS  65536

#define SENTINEL 0xFFFFFFFFu

// ---------------------------------------------------------------------------
// Scratch (device globals — allocation is forbidden)
// ---------------------------------------------------------------------------
__device__ float g_PRE [4 * T_SEQ * GATES];
__device__ float g_h0  [2 * T_SEQ * 512];
__device__ float g_h1  [2 * T_SEQ * 512];
__device__ float g_fc1 [2 * T_SEQ * D_H1];
__device__ float g_enc [2 * T_SEQ * D_H2];
__device__ float g_P   [2 * T_SEQ * D_H3];
__device__ float g_Ws  [D_H3 * D_H2];
__device__ float g_bs  [2 * GATES];

// ---------------------------------------------------------------------------
// Fast nonlinearities (MUFU-backed, ~1e-7 rel err)
// ---------------------------------------------------------------------------
__device__ __forceinline__ float sig_f(float x)
{
    return __fdividef(1.f, 1.f + __expf(-x));
}
__device__ __forceinline__ float tanh_f(float x)
{
    return __fdividef(2.f, 1.f + __expf(-2.f * x)) - 1.f;
}

// ---------------------------------------------------------------------------
// Re-sentinel LSTM output buffers (fallback path only)
// ---------------------------------------------------------------------------
__global__ void init_sent_kernel()
{
    unsigned idx = blockIdx.x * blockDim.x + threadIdx.x;
    const unsigned total = 2u * T_SEQ * 512u;
    if (idx < total) {
        ((unsigned*)g_h0)[idx] = SENTINEL;
        ((unsigned*)g_h1)[idx] = SENTINEL;
    }
}

// ---------------------------------------------------------------------------
// Layer-0 input gates, 16 timesteps per CTA (weights register-resident).
// grid (4, 128, 4), block 256
// ---------------------------------------------------------------------------
__global__ void __launch_bounds__(256) pre0_kernel(
    const float* __restrict__ v_r, const float* __restrict__ v_l,
    const float* __restrict__ Wih0,
    const float* __restrict__ bih0, const float* __restrict__ bhh0)
{
    const int g     = blockIdx.x * 256 + threadIdx.x;   // 0..1023
    const int tbase = blockIdx.y * 16;
    const int seq   = blockIdx.z;
    const int chain = seq >> 1, dir = seq & 1;

    __shared__ float vs[16][IN_DIM + 2];
    const float* v = (chain ? v_l : v_r) + (size_t)tbase * IN_DIM;
    for (int i = threadIdx.x; i < 16 * IN_DIM; i += 256)
        vs[i / IN_DIM][i % IN_DIM] = v[i];
    __syncthreads();

    float wr[IN_DIM];
    const float* wp = Wih0 + ((size_t)dir * GATES + g) * IN_DIM;
#pragma unroll
    for (int k = 0; k < IN_DIM; k++) wr[k] = __ldg(wp + k);
    const float b = bih0[dir * GATES + g] + bhh0[dir * GATES + g];

    float* outp = g_PRE + ((size_t)seq * T_SEQ + tbase) * GATES + g;
#pragma unroll
    for (int tt = 0; tt < 16; tt++) {
        float s = b;
#pragma unroll
        for (int k = 0; k < IN_DIM; k++) s = fmaf(wr[k], vs[tt][k], s);
        outp[(size_t)tt * GATES] = s;
    }
}

// ---------------------------------------------------------------------------
// Combined layer-1 biases / Ws = W3[:, :H2] + W3[:, H2:]
// ---------------------------------------------------------------------------
__global__ void bsum_kernel(const float* __restrict__ bih1,
                            const float* __restrict__ bhh1)
{
    int i = blockIdx.x * 256 + threadIdx.x;
    if (i < 2 * GATES) g_bs[i] = bih1[i] + bhh1[i];
}

__global__ void ws_kernel(const float* __restrict__ W3)
{
    int idx = blockIdx.x * 256 + threadIdx.x;
    if (idx < D_H3 * D_H2) {
        int i = idx >> 9;
        int j = idx & 511;
        g_Ws[idx] = W3[(size_t)i * (2 * D_H2) + j]
                  + W3[(size_t)i * (2 * D_H2) + D_H2 + j];
    }
}

// ---------------------------------------------------------------------------
// CLUSTER BiLSTM layer. grid = 64 CTAs, clusterDim = 16 (one cluster per
// sequence). CTA c owns 16 hidden units = 64 gate rows; layout as R13.
// Transport: producers PUSH h into all 15 peers' smem mailboxes (mapa +
// st.shared::cluster); consumers poll LOCAL smem and self-reset the slot.
// NEW (R14): TWO barriers per step — producers gather the 16 partials
// directly from part[] (conflict-free LDS) and carry the 4 prevals
// themselves; the gate_s stage + third barrier are deleted.
// ---------------------------------------------------------------------------
__global__ void __launch_bounds__(256, 1) lstm_cluster_kernel(
    const float* __restrict__ PRE,    // [4][T][1024]
    const float* __restrict__ Whh,    // [2][1024][256]
    float* __restrict__ HB)           // [2][T][512]
{
    const int bx    = blockIdx.x;           // 0..63
    const int seq   = bx >> 4;              // 0..3  (cluster id)
    const int c     = bx & 15;              // chunk = cluster rank
    const int chain = seq >> 1, dir = seq & 1;
    const int tid   = threadIdx.x;
    const int rloc  = tid & 63;             // local gate row
    const int kq    = tid >> 6;             // K quarter 0..3
    const int gidx  = rloc >> 4;            // gate (i,f,g,o)
    const int jl    = rloc & 15;            // unit within chunk
    const int grow  = (gidx << 8) + (c << 4) + jl;   // global gate row

    __shared__ __align__(16) float h_s[2][256];
    __shared__ unsigned mbox[2][256];       // mailbox, sentinel protocol
    __shared__ float part[256];

    // Recurrent weights for this (row, K-quarter) in registers.
    float w[64];
    {
        const float* wp = Whh + ((size_t)dir * GATES + grow) * HID + kq * 64;
#pragma unroll
        for (int i = 0; i < 64; i += 4) {
            float4 v = *(const float4*)(wp + i);
            w[i] = v.x; w[i + 1] = v.y; w[i + 2] = v.z; w[i + 3] = v.w;
        }
    }

    float* hbc = HB + (size_t)chain * T_SEQ * 512;
    // Producer-side PRE base: rows (g<<8) + (c<<4) + u for u = tid
    const float* preP = PRE + (size_t)seq * T_SEQ * GATES + (c << 4) + tid;

    const bool own    = ((tid >> 4) == c);   // comp tid produced locally
    const bool isprod = (tid < 16);          // producer: unit u = tid
    float cstate = 0.f;

    const uint32_t mbox_u32 = (uint32_t)__cvta_generic_to_shared(&mbox[0][0]);
    const uint32_t mypoll   = mbox_u32 + (tid << 2);   // mbox[0][tid]

    // Peer mailbox addresses for this producer's component.
    uint32_t peerAddr[15];
    if (isprod) {
        uint32_t myaddr = mbox_u32 + (((c << 4) + tid) << 2);
#pragma unroll
        for (int p = 0; p < 15; p++) {
            int rank = p + (p >= c ? 1 : 0);
            asm("mapa.shared::cluster.u32 %0, %1, %2;"
                : "=r"(peerAddr[p]) : "r"(myaddr), "r"(rank));
        }
    }

    h_s[0][tid] = 0.f;                      // h_{-1} = 0
    h_s[1][tid] = 0.f;
    mbox[0][tid] = SENTINEL;
    mbox[1][tid] = SENTINEL;
    __syncthreads();
    asm volatile("barrier.cluster.arrive.aligned;" ::: "memory");
    asm volatile("barrier.cluster.wait.aligned;" ::: "memory");

    for (int t = 0; t < T_SEQ; t++) {
        const int t_act = dir ? (T_SEQ - 1 - t) : t;
        const int par   = t & 1;

        // Producer-side input-gate prefetch (4 rows; overlaps the poll)
        float pv[4];
        if (isprod) {
            const float* pp = preP + (size_t)t_act * GATES;
#pragma unroll
            for (int g2 = 0; g2 < 4; g2++)
                pv[g2] = __ldg(pp + (g2 << 8));
        }

        if (t > 0 && !own) {
            const uint32_t a = mypoll + (par << 10);
            unsigned v;
            do {
                asm volatile("ld.volatile.shared.u32 %0, [%1];"
                             : "=r"(v) : "r"(a));
            } while (v == SENTINEL);
            asm volatile("st.shared.u32 [%0], %1;" :: "r"(a), "r"(SENTINEL));
            h_s[par][tid] = __uint_as_float(v);
        }
        __syncthreads();                    // bar1: h_s[par] complete

        // 64-MAC partial matvec over smem-broadcast h
        const float* hp = &h_s[par][kq << 6];
        float a0 = 0.f, a1 = 0.f, a2 = 0.f, a3 = 0.f;
#pragma unroll
        for (int i = 0; i < 64; i += 4) {
            float4 hv = *(const float4*)(hp + i);
            a0 = fmaf(w[i],     hv.x, a0);
            a1 = fmaf(w[i + 1], hv.y, a1);
            a2 = fmaf(w[i + 2], hv.z, a2);
            a3 = fmaf(w[i + 3], hv.w, a3);
        }
        part[tid] = (a0 + a1) + (a2 + a3);
        __syncthreads();                    // bar2: part[] complete

        if (isprod) {
            // Gather 16 partials: row (g<<4)+tid, K-quarter kq2
            float gi = pv[0], gf = pv[1], gg = pv[2], go = pv[3];
#pragma unroll
            for (int kq2 = 0; kq2 < 4; kq2++) {
                const int b = (kq2 << 6) + tid;
                gi += part[b];
                gf += part[b + 16];
                gg += part[b + 32];
                go += part[b + 48];
            }
            cstate = sig_f(gf) * cstate + sig_f(gi) * tanh_f(gg);
            float h = sig_f(go) * tanh_f(cstate);
            h_s[par ^ 1][(c << 4) + tid] = h;          // own comp, next step
            hbc[(size_t)t_act * 512 + dir * 256 + (c << 4) + tid] = h;
            if (t < T_SEQ - 1) {
                unsigned hv = __float_as_uint(h);
                const uint32_t off = (unsigned)(par ^ 1) << 10;
#pragma unroll
                for (int p = 0; p < 15; p++)
                    asm volatile("st.shared::cluster.u32 [%0], %1;"
                                 :: "r"(peerAddr[p] + off), "r"(hv));
            }
        }
        // no bar3: part[] is only overwritten after next step's bar1,
        // which producers reach only after reading part[] above.
    }
}

// ---------------------------------------------------------------------------
// FALLBACK BiLSTM layer (R9 exact): L2 sentinel polling, grid 64, block 256.
// ---------------------------------------------------------------------------
__global__ void __launch_bounds__(256, 1) lstm_kernel(
    const float* __restrict__ PRE,
    const float* __restrict__ Whh,
    float* __restrict__ HB)           // sentinel-initialized
{
    const int bx    = blockIdx.x;
    const int seq   = bx >> 4;
    const int c     = bx & 15;
    const int chain = seq >> 1, dir = seq & 1;
    const int tid   = threadIdx.x;
    const int rloc  = tid & 63;
    const int kq    = tid >> 6;
    const int gidx  = rloc >> 4;
    const int jl    = rloc & 15;
    const int grow  = (gidx << 8) + (c << 4) + jl;

    __shared__ __align__(16) float h_s[256];
    __shared__ float part[256];
    __shared__ float gate_s[64];

    float w[64];
    {
        const float* wp = Whh + ((size_t)dir * GATES + grow) * HID + kq * 64;
#pragma unroll
        for (int i = 0; i < 64; i += 4) {
            float4 v = *(const float4*)(wp + i);
            w[i] = v.x; w[i + 1] = v.y; w[i + 2] = v.z; w[i + 3] = v.w;
        }
    }

    float* hbc = HB + (size_t)chain * T_SEQ * 512;
    const float* prebase = PRE + (size_t)seq * T_SEQ * GATES + grow;
    const int  col = dir * 256 + tid;
    const bool own = ((tid >> 4) == c);
    float cstate = 0.f;

    h_s[tid] = 0.f;
    __syncthreads();

    for (int t = 0; t < T_SEQ; t++) {
        const int t_act = dir ? (T_SEQ - 1 - t) : t;

        float preval = 0.f;
        if (tid < 64)
            preval = __ldg(prebase + (size_t)t_act * GATES);

        if (t > 0 && !own) {
            const int p_act = dir ? (t_act + 1) : (t_act - 1);
            const unsigned* pp =
                (const unsigned*)(hbc + (size_t)p_act * 512 + col);
            unsigned v;
            do {
                asm volatile("ld.volatile.global.u32 %0, [%1];"
                             : "=r"(v) : "l"(pp));
            } while (v == SENTINEL);
            h_s[tid] = __uint_as_float(v);
        }
        __syncthreads();

        const float* hp = h_s + (kq << 6);
        float a0 = 0.f, a1 = 0.f, a2 = 0.f, a3 = 0.f;
#pragma unroll
        for (int i = 0; i < 64; i += 4) {
            float4 hv = *(const float4*)(hp + i);
            a0 = fmaf(w[i],     hv.x, a0);
            a1 = fmaf(w[i + 1], hv.y, a1);
            a2 = fmaf(w[i + 2], hv.z, a2);
            a3 = fmaf(w[i + 3], hv.w, a3);
        }
        part[tid] = (a0 + a1) + (a2 + a3);
        __syncthreads();

        if (tid < 64)
            gate_s[tid] = preval + part[tid] + part[tid + 64]
                        + part[tid + 128] + part[tid + 192];
        __syncthreads();

        if (tid < 16) {
            float gi = gate_s[tid];
            float gf = gate_s[16 + tid];
            float gg = gate_s[32 + tid];
            float go = gate_s[48 + tid];
            cstate = sig_f(gf) * cstate + sig_f(gi) * tanh_f(gg);
            float h = sig_f(go) * tanh_f(cstate);
            h_s[(c << 4) + tid] = h;
            unsigned hv = __float_as_uint(h);
            unsigned* dst = (unsigned*)(hbc + (size_t)t_act * 512
                                        + dir * 256 + (c << 4) + tid);
            asm volatile("st.volatile.global.u32 [%0], %1;" :: "l"(dst), "r"(hv));
        }
        __syncthreads();
    }
}

// ---------------------------------------------------------------------------
// SGEMM: C = act( alpha * ( A[M,K] @ B[N,K]^T + bias[N] ) )
// 128x128 tile, BK=8, 256 threads, 8x8 microtile.
// NEW (R14): double-buffered smem (2 stages) -> ONE barrier per K-tile;
// __launch_bounds__(256,2) for 2 CTAs/SM.
// ---------------------------------------------------------------------------
__global__ void __launch_bounds__(256, 2) gemm_kernel(
    const float* __restrict__ A, const float* __restrict__ B,
    const float* __restrict__ bias, float* __restrict__ C,
    int M, int N, int K, float alpha, int relu,
    long sA, long sB, long sBias, long sC, int aDiv, int bMod)
{
    A    += (size_t)(blockIdx.z / aDiv) * sA;
    B    += (size_t)(blockIdx.z % bMod) * sB;
    bias += (size_t)(blockIdx.z % bMod) * sBias;
    C    += (size_t)blockIdx.z * sC;

    __shared__ __align__(16) float As[2][8][132];
    __shared__ __align__(16) float Bs[2][8][132];

    const int tid = threadIdx.x;
    const int tx = tid & 15, ty = tid >> 4;
    const int m0 = blockIdx.y * 128, n0 = blockIdx.x * 128;
    const int lrow = tid >> 1;
    const int lk   = (tid & 1) << 2;

    float acc[8][8];
#pragma unroll
    for (int i = 0; i < 8; i++)
#pragma unroll
        for (int j = 0; j < 8; j++) acc[i][j] = 0.f;

    const float* Ap = A + (size_t)(m0 + lrow) * K + lk;
    const float* Bp = B + (size_t)(n0 + lrow) * K + lk;

    // Prologue: load tile 0 into stage 0
    {
        float4 av = *(const float4*)(Ap);
        float4 bv = *(const float4*)(Bp);
        As[0][lk + 0][lrow] = av.x; As[0][lk + 1][lrow] = av.y;
        As[0][lk + 2][lrow] = av.z; As[0][lk + 3][lrow] = av.w;
        Bs[0][lk + 0][lrow] = bv.x; Bs[0][lk + 1][lrow] = bv.y;
        Bs[0][lk + 2][lrow] = bv.z; Bs[0][lk + 3][lrow] = bv.w;
    }
    __syncthreads();

    int s = 0;
    for (int k0 = 0; k0 < K; k0 += 8) {
        float4 av, bv;
        const bool more = (k0 + 8 < K);
        if (more) {
            av = *(const float4*)(Ap + k0 + 8);
            bv = *(const float4*)(Bp + k0 + 8);
        }

#pragma unroll
        for (int kk = 0; kk < 8; kk++) {
            float4 va0 = *(const float4*)&As[s][kk][tx << 2];
            float4 va1 = *(const float4*)&As[s][kk][64 + (tx << 2)];
            float4 vb0 = *(const float4*)&Bs[s][kk][ty << 2];
            float4 vb1 = *(const float4*)&Bs[s][kk][64 + (ty << 2)];
            float ar[8] = {va0.x, va0.y, va0.z, va0.w,
                           va1.x, va1.y, va1.z, va1.w};
            float br[8] = {vb0.x, vb0.y, vb0.z, vb0.w,
                           vb1.x, vb1.y, vb1.z, vb1.w};
#pragma unroll
            for (int i = 0; i < 8; i++)
#pragma unroll
                for (int j = 0; j < 8; j++)
                    acc[i][j] = fmaf(ar[i], br[j], acc[i][j]);
        }

        if (more) {
            const int d = s ^ 1;
            As[d][lk + 0][lrow] = av.x; As[d][lk + 1][lrow] = av.y;
            As[d][lk + 2][lrow] = av.z; As[d][lk + 3][lrow] = av.w;
            Bs[d][lk + 0][lrow] = bv.x; Bs[d][lk + 1][lrow] = bv.y;
            Bs[d][lk + 2][lrow] = bv.z; Bs[d][lk + 3][lrow] = bv.w;
        }
        __syncthreads();
        s ^= 1;
    }

    float bia[8];
#pragma unroll
    for (int j = 0; j < 8; j++) {
        int n = n0 + ((j < 4) ? (ty << 2) + j : 64 + (ty << 2) + (j - 4));
        bia[j] = bias[n];
    }

#pragma unroll
    for (int i = 0; i < 8; i++) {
        int m = m0 + ((i < 4) ? (tx << 2) + i : 64 + (tx << 2) + (i - 4));
        float v[8];
#pragma unroll
        for (int j = 0; j < 8; j++) {
            float x = alpha * (acc[i][j] + bia[j]);
            v[j] = relu ? fmaxf(x, 0.f) : x;
        }
        float4 o0 = {v[0], v[1], v[2], v[3]};
        float4 o1 = {v[4], v[5], v[6], v[7]};
        *(float4*)(C + (size_t)m * N + n0 + (ty << 2))      = o0;
        *(float4*)(C + (size_t)m * N + n0 + 64 + (ty << 2)) = o1;
    }
}

// ---------------------------------------------------------------------------
// Pair stage: logits[p] = relu(P_r[pr] + P_l[pl]) . Wout^T + bout; log_softmax
// ---------------------------------------------------------------------------
__global__ void __launch_bounds__(256) pair_kernel(
    const int* __restrict__ pair_r, const int* __restrict__ pair_l,
    const float* __restrict__ Wout, const float* __restrict__ bout,
    float* __restrict__ out)
{
    __shared__ float w0[D_H3], w1[D_H3];
    for (int i = threadIdx.x; i < D_H3; i += 256) {
        w0[i] = Wout[i];
        w1[i] = Wout[D_H3 + i];
    }
    __syncthreads();

    const int warp = threadIdx.x >> 5, lane = threadIdx.x & 31;
    const float b0 = bout[0], b1 = bout[1];
    const float* Pr_base = g_P;
    const float* Pl_base = g_P + (size_t)T_SEQ * D_H3;

    for (int p = blockIdx.x * 8 + warp; p < NPAIRS; p += gridDim.x * 8) {
        const float4* Pr = (const float4*)(Pr_base + (size_t)pair_r[p] * D_H3);
        const float4* Pl = (const float4*)(Pl_base + (size_t)pair_l[p] * D_H3);
        float a0 = 0.f, a1 = 0.f;
#pragma unroll 4
        for (int k4 = lane; k4 < D_H3 / 4; k4 += 32) {
            float4 r = __ldg(Pr + k4);
            float4 l = __ldg(Pl + k4);
            int kb = k4 << 2;
            float s0 = fmaxf(r.x + l.x, 0.f);
            float s1 = fmaxf(r.y + l.y, 0.f);
            float s2 = fmaxf(r.z + l.z, 0.f);
            float s3 = fmaxf(r.w + l.w, 0.f);
            a0 = fmaf(s0, w0[kb], a0);     a1 = fmaf(s0, w1[kb], a1);
            a0 = fmaf(s1, w0[kb + 1], a0); a1 = fmaf(s1, w1[kb + 1], a1);
            a0 = fmaf(s2, w0[kb + 2], a0); a1 = fmaf(s2, w1[kb + 2], a1);
            a0 = fmaf(s3, w0[kb + 3], a0); a1 = fmaf(s3, w1[kb + 3], a1);
        }
#pragma unroll
        for (int off = 16; off > 0; off >>= 1) {
            a0 += __shfl_down_sync(0xFFFFFFFFu, a0, off);
            a1 += __shfl_down_sync(0xFFFFFFFFu, a1, off);
        }
        if (lane == 0) {
            float l0 = a0 + b0, l1 = a1 + b1;
            float m = fmaxf(l0, l1);
            float lse = m + logf(expf(l0 - m) + expf(l1 - m));
            out[2 * p]     = l0 - lse;
            out[2 * p + 1] = l1 - lse;
        }
    }
}

// ---------------------------------------------------------------------------
// Host
// ---------------------------------------------------------------------------
extern "C" void kernel_launch(void* const* d_in, const int* in_sizes, int n_in,
                              void* d_out, int out_size)
{
    const float* v_r    = (const float*)d_in[0];
    const float* v_l    = (const float*)d_in[1];
    const int*   pair_r = (const int*)  d_in[2];
    const int*   pair_l = (const int*)  d_in[3];
    const float* Wih0   = (const float*)d_in[4];
    const float* Whh0   = (const float*)d_in[5];
    const float* bih0   = (const float*)d_in[6];
    const float* bhh0   = (const float*)d_in[7];
    const float* Wih1   = (const float*)d_in[8];
    const float* Whh1   = (const float*)d_in[9];
    const float* bih1   = (const float*)d_in[10];
    const float* bhh1   = (const float*)d_in[11];
    const float* W1     = (const float*)d_in[12];
    const float* b1     = (const float*)d_in[13];
    const float* W2     = (const float*)d_in[14];
    const float* b2     = (const float*)d_in[15];
    const float* W3     = (const float*)d_in[16];
    const float* b3     = (const float*)d_in[17];
    const float* Wout   = (const float*)d_in[18];
    const float* bout   = (const float*)d_in[19];
    float* out = (float*)d_out;

    float *PRE, *H0, *H1, *FC1, *ENC, *PT, *WS, *BS;
    cudaGetSymbolAddress((void**)&PRE, g_PRE);
    cudaGetSymbolAddress((void**)&H0,  g_h0);
    cudaGetSymbolAddress((void**)&H1,  g_h1);
    cudaGetSymbolAddress((void**)&FC1, g_fc1);
    cudaGetSymbolAddress((void**)&ENC, g_enc);
    cudaGetSymbolAddress((void**)&PT,  g_P);
    cudaGetSymbolAddress((void**)&WS,  g_Ws);
    cudaGetSymbolAddress((void**)&BS,  g_bs);

    // --- Probe cluster-16 support (pure host query, capture-safe) ---
    cudaFuncSetAttribute(lstm_cluster_kernel,
                         cudaFuncAttributeNonPortableClusterSizeAllowed, 1);
    cudaLaunchConfig_t cfg = {};
    cfg.gridDim  = dim3(64, 1, 1);
    cfg.blockDim = dim3(256, 1, 1);
    cudaLaunchAttribute attrs[1];
    attrs[0].id = cudaLaunchAttributeClusterDimension;
    attrs[0].val.clusterDim = {16, 1, 1};
    cfg.attrs = attrs;
    cfg.numAttrs = 1;
    int numClusters = 0;
    cudaError_t qe = cudaOccupancyMaxActiveClusters(
        &numClusters, lstm_cluster_kernel, &cfg);
    bool use_cluster = (qe == cudaSuccess && numClusters >= 4);
    if (!use_cluster) cudaGetLastError();   // clear sticky error

    // 1. Precomputes
    pre0_kernel<<<dim3(4, 128, 4), 256>>>(v_r, v_l, Wih0, bih0, bhh0);
    bsum_kernel<<<8, 256>>>(bih1, bhh1);

    // 2. LSTM layer 0
    if (use_cluster) {
        cudaLaunchKernelEx(&cfg, lstm_cluster_kernel,
                           (const float*)PRE, Whh0, H0);
    } else {
        init_sent_kernel<<<(2 * T_SEQ * 512 + 255) / 256, 256>>>();
        lstm_kernel<<<64, 256>>>(PRE, Whh0, H0);
    }

    // 3. Layer-1 input gates, batched over seq (z=4)
    gemm_kernel<<<dim3(GATES / 128, T_SEQ / 128, 4), 256>>>(
        H0, Wih1, BS, PRE, T_SEQ, GATES, 512, 1.f, 0,
        (long)T_SEQ * 512, (long)GATES * 512, (long)GATES,
        (long)T_SEQ * GATES, 2, 2);

    // 4. LSTM layer 1
    if (use_cluster) {
        cudaLaunchKernelEx(&cfg, lstm_cluster_kernel,
                           (const float*)PRE, Whh1, H1);
    } else {
        lstm_kernel<<<64, 256>>>(PRE, Whh1, H1);
    }

    // 5. MLP encoders, batched over chain (z=2)
    gemm_kernel<<<dim3(D_H1 / 128, T_SEQ / 128, 2), 256>>>(
        H1, W1, b1, FC1, T_SEQ, D_H1, 512, 1.f, 1,
        (long)T_SEQ * 512, 0, 0, (long)T_SEQ * D_H1, 1, 1);

    gemm_kernel<<<dim3(D_H2 / 128, T_SEQ / 128, 2), 256>>>(
        FC1, W2, b2, ENC, T_SEQ, D_H2, D_H1, 1.f, 1,
        (long)T_SEQ * D_H1, 0, 0, (long)T_SEQ * D_H2, 1, 1);

    ws_kernel<<<(D_H3 * D_H2 + 255) / 256, 256>>>(W3);

    // P = 0.5*(enc @ Ws^T + b3)
    gemm_kernel<<<dim3(D_H3 / 128, T_SEQ / 128, 2), 256>>>(
        ENC, WS, b3, PT, T_SEQ, D_H3, D_H2, 0.5f, 0,
        (long)T_SEQ * D_H2, 0, 0, (long)T_SEQ * D_H3, 1, 1);

    // 6. Pair gather + dot + log_softmax
    pair_kernel<<<2048, 256>>>(pair_r, pair_l, Wout, bout, out);
}

// round 15
// speedup vs baseline: 1.7334x; 1.0169x over previous
#include <cuda_runtime.h>
#include <cuda_bf16.h>
#include <cstdint>
#include <cstddef>
#include <math.h>

// ---------------------------------------------------------------------------
// Problem constants
// ---------------------------------------------------------------------------
#define T_SEQ   2048
#define HID     256
#define GATES   1024      // 4*HID
#define IN_DIM  22
#define D_H1    1024
#define D_H2    512
#define D_H3    1024
#define NPAIRS  65536

#define SENTINEL 0xFFFFFFFFu

// ---------------------------------------------------------------------------
// Scratch (device globals — allocation is forbidden)
// ---------------------------------------------------------------------------
__device__ float g_PRE [4 * T_SEQ * GATES];
__device__ float g_h0  [2 * T_SEQ * 512];
__device__ float g_h1  [2 * T_SEQ * 512];
__device__ float g_fc1 [2 * T_SEQ * D_H1];
__device__ float g_enc [2 * T_SEQ * D_H2];
__device__ float g_P   [2 * T_SEQ * D_H3];
__device__ float g_Ws  [D_H3 * D_H2];
__device__ float g_bs  [2 * GATES];

// ---------------------------------------------------------------------------
// Packed f32x2 helpers
// ---------------------------------------------------------------------------
#define PACK2(out, lo, hi) \
    asm("mov.b64 %0, {%1, %2};" : "=l"(out) : "f"(lo), "f"(hi))
#define UNPACK2(lo, hi, in) \
    asm("mov.b64 {%0, %1}, %2;" : "=f"(lo), "=f"(hi) : "l"(in))
#define FMA2(acc, a, b) \
    asm("fma.rn.f32x2 %0, %1, %2, %0;" : "+l"(acc) : "l"(a), "l"(b))

// ---------------------------------------------------------------------------
// Fast nonlinearities (MUFU-backed, ~1e-7 rel err)
// ---------------------------------------------------------------------------
__device__ __forceinline__ float sig_f(float x)
{
    return __fdividef(1.f, 1.f + __expf(-x));
}
__device__ __forceinline__ float tanh_f(float x)
{
    return __fdividef(2.f, 1.f + __expf(-2.f * x)) - 1.f;
}

// ---------------------------------------------------------------------------
// Re-sentinel LSTM output buffers (fallback path only)
// ---------------------------------------------------------------------------
__global__ void init_sent_kernel()
{
    unsigned idx = blockIdx.x * blockDim.x + threadIdx.x;
    const unsigned total = 2u * T_SEQ * 512u;
    if (idx < total) {
        ((unsigned*)g_h0)[idx] = SENTINEL;
        ((unsigned*)g_h1)[idx] = SENTINEL;
    }
}

// ---------------------------------------------------------------------------
// Layer-0 input gates, 16 timesteps per CTA (weights register-resident).
// grid (4, 128, 4), block 256
// ---------------------------------------------------------------------------
__global__ void __launch_bounds__(256) pre0_kernel(
    const float* __restrict__ v_r, const float* __restrict__ v_l,
    const float* __restrict__ Wih0,
    const float* __restrict__ bih0, const float* __restrict__ bhh0)
{
    const int g     = blockIdx.x * 256 + threadIdx.x;   // 0..1023
    const int tbase = blockIdx.y * 16;
    const int seq   = blockIdx.z;
    const int chain = seq >> 1, dir = seq & 1;

    __shared__ float vs[16][IN_DIM + 2];
    const float* v = (chain ? v_l : v_r) + (size_t)tbase * IN_DIM;
    for (int i = threadIdx.x; i < 16 * IN_DIM; i += 256)
        vs[i / IN_DIM][i % IN_DIM] = v[i];
    __syncthreads();

    float wr[IN_DIM];
    const float* wp = Wih0 + ((size_t)dir * GATES + g) * IN_DIM;
#pragma unroll
    for (int k = 0; k < IN_DIM; k++) wr[k] = __ldg(wp + k);
    const float b = bih0[dir * GATES + g] + bhh0[dir * GATES + g];

    float* outp = g_PRE + ((size_t)seq * T_SEQ + tbase) * GATES + g;
#pragma unroll
    for (int tt = 0; tt < 16; tt++) {
        float s = b;
#pragma unroll
        for (int k = 0; k < IN_DIM; k++) s = fmaf(wr[k], vs[tt][k], s);
        outp[(size_t)tt * GATES] = s;
    }
}

// ---------------------------------------------------------------------------
// Combined layer-1 biases / Ws = W3[:, :H2] + W3[:, H2:]
// ---------------------------------------------------------------------------
__global__ void bsum_kernel(const float* __restrict__ bih1,
                            const float* __restrict__ bhh1)
{
    int i = blockIdx.x * 256 + threadIdx.x;
    if (i < 2 * GATES) g_bs[i] = bih1[i] + bhh1[i];
}

__global__ void ws_kernel(const float* __restrict__ W3)
{
    int idx = blockIdx.x * 256 + threadIdx.x;
    if (idx < D_H3 * D_H2) {
        int i = idx >> 9;
        int j = idx & 511;
        g_Ws[idx] = W3[(size_t)i * (2 * D_H2) + j]
                  + W3[(size_t)i * (2 * D_H2) + D_H2 + j];
    }
}

// ---------------------------------------------------------------------------
// CLUSTER BiLSTM layer. grid = 64 CTAs, clusterDim = 16 (one cluster per
// sequence). CTA c owns 16 hidden units = 64 gate rows. Producers PUSH h
// into all 15 peers' smem mailboxes (mapa + st.shared::cluster) — FIRST,
// before any local/global stores, since the DSMEM landing latency gates
// every consumer's next step. Consumers poll LOCAL smem, self-reset slots.
// Two barriers per step; producers gather partials directly from part[].
// ---------------------------------------------------------------------------
__global__ void __launch_bounds__(256, 1) lstm_cluster_kernel(
    const float* __restrict__ PRE,    // [4][T][1024]
    const float* __restrict__ Whh,    // [2][1024][256]
    float* __restrict__ HB)           // [2][T][512]
{
    const int bx    = blockIdx.x;           // 0..63
    const int seq   = bx >> 4;              // 0..3  (cluster id)
    const int c     = bx & 15;              // chunk = cluster rank
    const int chain = seq >> 1, dir = seq & 1;
    const int tid   = threadIdx.x;
    const int rloc  = tid & 63;             // local gate row
    const int kq    = tid >> 6;             // K quarter 0..3
    const int gidx  = rloc >> 4;            // gate (i,f,g,o)
    const int jl    = rloc & 15;            // unit within chunk
    const int grow  = (gidx << 8) + (c << 4) + jl;   // global gate row

    __shared__ __align__(16) float h_s[2][256];
    __shared__ unsigned mbox[2][256];       // mailbox, sentinel protocol
    __shared__ float part[256];

    // Recurrent weights for this (row, K-quarter) in registers.
    float w[64];
    {
        const float* wp = Whh + ((size_t)dir * GATES + grow) * HID + kq * 64;
#pragma unroll
        for (int i = 0; i < 64; i += 4) {
            float4 v = *(const float4*)(wp + i);
            w[i] = v.x; w[i + 1] = v.y; w[i + 2] = v.z; w[i + 3] = v.w;
        }
    }

    float* hbc = HB + (size_t)chain * T_SEQ * 512;
    // Producer-side PRE base: rows (g<<8) + (c<<4) + u for u = tid
    const float* preP = PRE + (size_t)seq * T_SEQ * GATES + (c << 4) + tid;

    const bool own    = ((tid >> 4) == c);   // comp tid produced locally
    const bool isprod = (tid < 16);          // producer: unit u = tid
    float cstate = 0.f;

    const uint32_t mbox_u32 = (uint32_t)__cvta_generic_to_shared(&mbox[0][0]);
    const uint32_t mypoll   = mbox_u32 + (tid << 2);   // mbox[0][tid]

    // Peer mailbox addresses for this producer's component.
    uint32_t peerAddr[15];
    if (isprod) {
        uint32_t myaddr = mbox_u32 + (((c << 4) + tid) << 2);
#pragma unroll
        for (int p = 0; p < 15; p++) {
            int rank = p + (p >= c ? 1 : 0);
            asm("mapa.shared::cluster.u32 %0, %1, %2;"
                : "=r"(peerAddr[p]) : "r"(myaddr), "r"(rank));
        }
    }

    h_s[0][tid] = 0.f;                      // h_{-1} = 0
    h_s[1][tid] = 0.f;
    mbox[0][tid] = SENTINEL;
    mbox[1][tid] = SENTINEL;
    __syncthreads();
    asm volatile("barrier.cluster.arrive.aligned;" ::: "memory");
    asm volatile("barrier.cluster.wait.aligned;" ::: "memory");

    for (int t = 0; t < T_SEQ; t++) {
        const int t_act = dir ? (T_SEQ - 1 - t) : t;
        const int par   = t & 1;

        // Producer-side input-gate prefetch (4 rows; overlaps the poll)
        float pv[4];
        if (isprod) {
            const float* pp = preP + (size_t)t_act * GATES;
#pragma unroll
            for (int g2 = 0; g2 < 4; g2++)
                pv[g2] = __ldg(pp + (g2 << 8));
        }

        if (t > 0 && !own) {
            const uint32_t a = mypoll + (par << 10);
            unsigned v;
            do {
                asm volatile("ld.volatile.shared.u32 %0, [%1];"
                             : "=r"(v) : "r"(a));
            } while (v == SENTINEL);
            asm volatile("st.shared.u32 [%0], %1;" :: "r"(a), "r"(SENTINEL));
            h_s[par][tid] = __uint_as_float(v);
        }
        __syncthreads();                    // bar1: h_s[par] complete

        // 64-MAC partial matvec over smem-broadcast h
        const float* hp = &h_s[par][kq << 6];
        float a0 = 0.f, a1 = 0.f, a2 = 0.f, a3 = 0.f;
#pragma unroll
        for (int i = 0; i < 64; i += 4) {
            float4 hv = *(const float4*)(hp + i);
            a0 = fmaf(w[i],     hv.x, a0);
            a1 = fmaf(w[i + 1], hv.y, a1);
            a2 = fmaf(w[i + 2], hv.z, a2);
            a3 = fmaf(w[i + 3], hv.w, a3);
        }
        part[tid] = (a0 + a1) + (a2 + a3);
        __syncthreads();                    // bar2: part[] complete

        if (isprod) {
            // Gather 16 partials: row (g<<4)+tid, K-quarter kq2
            float gi = pv[0], gf = pv[1], gg = pv[2], go = pv[3];
#pragma unroll
            for (int kq2 = 0; kq2 < 4; kq2++) {
                const int b = (kq2 << 6) + tid;
                gi += part[b];
                gf += part[b + 16];
                gg += part[b + 32];
                go += part[b + 48];
            }
            cstate = sig_f(gf) * cstate + sig_f(gi) * tanh_f(gg);
            float h = sig_f(go) * tanh_f(cstate);
            unsigned hv = __float_as_uint(h);
            // PUSH FIRST — DSMEM landing gates every consumer's next step.
            if (t < T_SEQ - 1) {
                const uint32_t off = (unsigned)(par ^ 1) << 10;
#pragma unroll
                for (int p = 0; p < 15; p++)
                    asm volatile("st.shared::cluster.u32 [%0], %1;"
                                 :: "r"(peerAddr[p] + off), "r"(hv));
            }
            h_s[par ^ 1][(c << 4) + tid] = h;          // own comp, next step
            hbc[(size_t)t_act * 512 + dir * 256 + (c << 4) + tid] = h;
        }
        // no bar3: part[] is only overwritten after next step's bar1,
        // which producers reach only after reading part[] above.
    }
}

// ---------------------------------------------------------------------------
// FALLBACK BiLSTM layer (R9 exact): L2 sentinel polling, grid 64, block 256.
// ---------------------------------------------------------------------------
__global__ void __launch_bounds__(256, 1) lstm_kernel(
    const float* __restrict__ PRE,
    const float* __restrict__ Whh,
    float* __restrict__ HB)           // sentinel-initialized
{
    const int bx    = blockIdx.x;
    const int seq   = bx >> 4;
    const int c     = bx & 15;
    const int chain = seq >> 1, dir = seq & 1;
    const int tid   = threadIdx.x;
    const int rloc  = tid & 63;
    const int kq    = tid >> 6;
    const int gidx  = rloc >> 4;
    const int jl    = rloc & 15;
    const int grow  = (gidx << 8) + (c << 4) + jl;

    __shared__ __align__(16) float h_s[256];
    __shared__ float part[256];
    __shared__ float gate_s[64];

    float w[64];
    {
        const float* wp = Whh + ((size_t)dir * GATES + grow) * HID + kq * 64;
#pragma unroll
        for (int i = 0; i < 64; i += 4) {
            float4 v = *(const float4*)(wp + i);
            w[i] = v.x; w[i + 1] = v.y; w[i + 2] = v.z; w[i + 3] = v.w;
        }
    }

    float* hbc = HB + (size_t)chain * T_SEQ * 512;
    const float* prebase = PRE + (size_t)seq * T_SEQ * GATES + grow;
    const int  col = dir * 256 + tid;
    const bool own = ((tid >> 4) == c);
    float cstate = 0.f;

    h_s[tid] = 0.f;
    __syncthreads();

    for (int t = 0; t < T_SEQ; t++) {
        const int t_act = dir ? (T_SEQ - 1 - t) : t;

        float preval = 0.f;
        if (tid < 64)
            preval = __ldg(prebase + (size_t)t_act * GATES);

        if (t > 0 && !own) {
            const int p_act = dir ? (t_act + 1) : (t_act - 1);
            const unsigned* pp =
                (const unsigned*)(hbc + (size_t)p_act * 512 + col);
            unsigned v;
            do {
                asm volatile("ld.volatile.global.u32 %0, [%1];"
                             : "=r"(v) : "l"(pp));
            } while (v == SENTINEL);
            h_s[tid] = __uint_as_float(v);
        }
        __syncthreads();

        const float* hp = h_s + (kq << 6);
        float a0 = 0.f, a1 = 0.f, a2 = 0.f, a3 = 0.f;
#pragma unroll
        for (int i = 0; i < 64; i += 4) {
            float4 hv = *(const float4*)(hp + i);
            a0 = fmaf(w[i],     hv.x, a0);
            a1 = fmaf(w[i + 1], hv.y, a1);
            a2 = fmaf(w[i + 2], hv.z, a2);
            a3 = fmaf(w[i + 3], hv.w, a3);
        }
        part[tid] = (a0 + a1) + (a2 + a3);
        __syncthreads();

        if (tid < 64)
            gate_s[tid] = preval + part[tid] + part[tid + 64]
                        + part[tid + 128] + part[tid + 192];
        __syncthreads();

        if (tid < 16) {
            float gi = gate_s[tid];
            float gf = gate_s[16 + tid];
            float gg = gate_s[32 + tid];
            float go = gate_s[48 + tid];
            cstate = sig_f(gf) * cstate + sig_f(gi) * tanh_f(gg);
            float h = sig_f(go) * tanh_f(cstate);
            h_s[(c << 4) + tid] = h;
            unsigned hv = __float_as_uint(h);
            unsigned* dst = (unsigned*)(hbc + (size_t)t_act * 512
                                        + dir * 256 + (c << 4) + tid);
            asm volatile("st.volatile.global.u32 [%0], %1;" :: "l"(dst), "r"(hv));
        }
        __syncthreads();
    }
}

// ---------------------------------------------------------------------------
// SGEMM: C = act( alpha * ( A[M,K] @ B[N,K]^T + bias[N] ) )
// 128x128 tile, BK=8, 256 threads, 8x8 microtile, double-buffered smem.
// NEW (R15): inner product uses packed fma.rn.f32x2 — 32 FFMA2 instead of
// 64 FFMA per kk — to exploit the sm_103a dual-rate f32x2 FMA path.
// ---------------------------------------------------------------------------
__global__ void __launch_bounds__(256, 2) gemm_kernel(
    const float* __restrict__ A, const float* __restrict__ B,
    const float* __restrict__ bias, float* __restrict__ C,
    int M, int N, int K, float alpha, int relu,
    long sA, long sB, long sBias, long sC, int aDiv, int bMod)
{
    A    += (size_t)(blockIdx.z / aDiv) * sA;
    B    += (size_t)(blockIdx.z % bMod) * sB;
    bias += (size_t)(blockIdx.z % bMod) * sBias;
    C    += (size_t)blockIdx.z * sC;

    __shared__ __align__(16) float As[2][8][132];
    __shared__ __align__(16) float Bs[2][8][132];

    const int tid = threadIdx.x;
    const int tx = tid & 15, ty = tid >> 4;
    const int m0 = blockIdx.y * 128, n0 = blockIdx.x * 128;
    const int lrow = tid >> 1;
    const int lk   = (tid & 1) << 2;

    unsigned long long acc2[8][4];
#pragma unroll
    for (int i = 0; i < 8; i++)
#pragma unroll
        for (int p = 0; p < 4; p++) acc2[i][p] = 0ULL;

    const float* Ap = A + (size_t)(m0 + lrow) * K + lk;
    const float* Bp = B + (size_t)(n0 + lrow) * K + lk;

    // Prologue: load tile 0 into stage 0
    {
        float4 av = *(const float4*)(Ap);
        float4 bv = *(const float4*)(Bp);
        As[0][lk + 0][lrow] = av.x; As[0][lk + 1][lrow] = av.y;
        As[0][lk + 2][lrow] = av.z; As[0][lk + 3][lrow] = av.w;
        Bs[0][lk + 0][lrow] = bv.x; Bs[0][lk + 1][lrow] = bv.y;
        Bs[0][lk + 2][lrow] = bv.z; Bs[0][lk + 3][lrow] = bv.w;
    }
    __syncthreads();

    int s = 0;
    for (int k0 = 0; k0 < K; k0 += 8) {
        float4 av, bv;
        const bool more = (k0 + 8 < K);
        if (more) {
            av = *(const float4*)(Ap + k0 + 8);
            bv = *(const float4*)(Bp + k0 + 8);
        }

#pragma unroll
        for (int kk = 0; kk < 8; kk++) {
            float4 va0 = *(const float4*)&As[s][kk][tx << 2];
            float4 va1 = *(const float4*)&As[s][kk][64 + (tx << 2)];
            float4 vb0 = *(const float4*)&Bs[s][kk][ty << 2];
            float4 vb1 = *(const float4*)&Bs[s][kk][64 + (ty << 2)];
            unsigned long long bp[4];
            PACK2(bp[0], vb0.x, vb0.y); PACK2(bp[1], vb0.z, vb0.w);
            PACK2(bp[2], vb1.x, vb1.y); PACK2(bp[3], vb1.z, vb1.w);
            float ar[8] = {va0.x, va0.y, va0.z, va0.w,
                           va1.x, va1.y, va1.z, va1.w};
#pragma unroll
            for (int i = 0; i < 8; i++) {
                unsigned long long aa;
                PACK2(aa, ar[i], ar[i]);
                FMA2(acc2[i][0], aa, bp[0]);
                FMA2(acc2[i][1], aa, bp[1]);
                FMA2(acc2[i][2], aa, bp[2]);
                FMA2(acc2[i][3], aa, bp[3]);
            }
        }

        if (more) {
            const int d = s ^ 1;
            As[d][lk + 0][lrow] = av.x; As[d][lk + 1][lrow] = av.y;
            As[d][lk + 2][lrow] = av.z; As[d][lk + 3][lrow] = av.w;
            Bs[d][lk + 0][lrow] = bv.x; Bs[d][lk + 1][lrow] = bv.y;
            Bs[d][lk + 2][lrow] = bv.z; Bs[d][lk + 3][lrow] = bv.w;
        }
        __syncthreads();
        s ^= 1;
    }

    float bia[8];
#pragma unroll
    for (int j = 0; j < 8; j++) {
        int n = n0 + ((j < 4) ? (ty << 2) + j : 64 + (ty << 2) + (j - 4));
        bia[j] = bias[n];
    }

#pragma unroll
    for (int i = 0; i < 8; i++) {
        int m = m0 + ((i < 4) ? (tx << 2) + i : 64 + (tx << 2) + (i - 4));
        float v[8];
#pragma unroll
        for (int p = 0; p < 4; p++) {
            float lo, hi;
            UNPACK2(lo, hi, acc2[i][p]);
            v[2 * p]     = lo;
            v[2 * p + 1] = hi;
        }
#pragma unroll
        for (int j = 0; j < 8; j++) {
            float x = alpha * (v[j] + bia[j]);
            v[j] = relu ? fmaxf(x, 0.f) : x;
        }
        float4 o0 = {v[0], v[1], v[2], v[3]};
        float4 o1 = {v[4], v[5], v[6], v[7]};
        *(float4*)(C + (size_t)m * N + n0 + (ty << 2))      = o0;
        *(float4*)(C + (size_t)m * N + n0 + 64 + (ty << 2)) = o1;
    }
}

// ---------------------------------------------------------------------------
// Pair stage: logits[p] = relu(P_r[pr] + P_l[pl]) . Wout^T + bout; log_softmax
// ---------------------------------------------------------------------------
__global__ void __launch_bounds__(256) pair_kernel(
    const int* __restrict__ pair_r, const int* __restrict__ pair_l,
    const float* __restrict__ Wout, const float* __restrict__ bout,
    float* __restrict__ out)
{
    __shared__ float w0[D_H3], w1[D_H3];
    for (int i = threadIdx.x; i < D_H3; i += 256) {
        w0[i] = Wout[i];
        w1[i] = Wout[D_H3 + i];
    }
    __syncthreads();

    const int warp = threadIdx.x >> 5, lane = threadIdx.x & 31;
    const float b0 = bout[0], b1 = bout[1];
    const float* Pr_base = g_P;
    const float* Pl_base = g_P + (size_t)T_SEQ * D_H3;

    for (int p = blockIdx.x * 8 + warp; p < NPAIRS; p += gridDim.x * 8) {
        const float4* Pr = (const float4*)(Pr_base + (size_t)pair_r[p] * D_H3);
        const float4* Pl = (const float4*)(Pl_base + (size_t)pair_l[p] * D_H3);
        float a0 = 0.f, a1 = 0.f;
#pragma unroll 4
        for (int k4 = lane; k4 < D_H3 / 4; k4 += 32) {
            float4 r = __ldg(Pr + k4);
            float4 l = __ldg(Pl + k4);
            int kb = k4 << 2;
            float s0 = fmaxf(r.x + l.x, 0.f);
            float s1 = fmaxf(r.y + l.y, 0.f);
            float s2 = fmaxf(r.z + l.z, 0.f);
            float s3 = fmaxf(r.w + l.w, 0.f);
            a0 = fmaf(s0, w0[kb], a0);     a1 = fmaf(s0, w1[kb], a1);
            a0 = fmaf(s1, w0[kb + 1], a0); a1 = fmaf(s1, w1[kb + 1], a1);
            a0 = fmaf(s2, w0[kb + 2], a0); a1 = fmaf(s2, w1[kb + 2], a1);
            a0 = fmaf(s3, w0[kb + 3], a0); a1 = fmaf(s3, w1[kb + 3], a1);
        }
#pragma unroll
        for (int off = 16; off > 0; off >>= 1) {
            a0 += __shfl_down_sync(0xFFFFFFFFu, a0, off);
            a1 += __shfl_down_sync(0xFFFFFFFFu, a1, off);
        }
        if (lane == 0) {
            float l0 = a0 + b0, l1 = a1 + b1;
            float m = fmaxf(l0, l1);
            float lse = m + logf(expf(l0 - m) + expf(l1 - m));
            out[2 * p]     = l0 - lse;
            out[2 * p + 1] = l1 - lse;
        }
    }
}

// ---------------------------------------------------------------------------
// Host
// ---------------------------------------------------------------------------
extern "C" void kernel_launch(void* const* d_in, const int* in_sizes, int n_in,
                              void* d_out, int out_size)
{
    const float* v_r    = (const float*)d_in[0];
    const float* v_l    = (const float*)d_in[1];
    const int*   pair_r = (const int*)  d_in[2];
    const int*   pair_l = (const int*)  d_in[3];
    const float* Wih0   = (const float*)d_in[4];
    const float* Whh0   = (const float*)d_in[5];
    const float* bih0   = (const float*)d_in[6];
    const float* bhh0   = (const float*)d_in[7];
    const float* Wih1   = (const float*)d_in[8];
    const float* Whh1   = (const float*)d_in[9];
    const float* bih1   = (const float*)d_in[10];
    const float* bhh1   = (const float*)d_in[11];
    const float* W1     = (const float*)d_in[12];
    const float* b1     = (const float*)d_in[13];
    const float* W2     = (const float*)d_in[14];
    const float* b2     = (const float*)d_in[15];
    const float* W3     = (const float*)d_in[16];
    const float* b3     = (const float*)d_in[17];
    const float* Wout   = (const float*)d_in[18];
    const float* bout   = (const float*)d_in[19];
    float* out = (float*)d_out;

    float *PRE, *H0, *H1, *FC1, *ENC, *PT, *WS, *BS;
    cudaGetSymbolAddress((void**)&PRE, g_PRE);
    cudaGetSymbolAddress((void**)&H0,  g_h0);
    cudaGetSymbolAddress((void**)&H1,  g_h1);
    cudaGetSymbolAddress((void**)&FC1, g_fc1);
    cudaGetSymbolAddress((void**)&ENC, g_enc);
    cudaGetSymbolAddress((void**)&PT,  g_P);
    cudaGetSymbolAddress((void**)&WS,  g_Ws);
    cudaGetSymbolAddress((void**)&BS,  g_bs);

    // --- Probe cluster-16 support (pure host query, capture-safe) ---
    cudaFuncSetAttribute(lstm_cluster_kernel,
                         cudaFuncAttributeNonPortableClusterSizeAllowed, 1);
    cudaLaunchConfig_t cfg = {};
    cfg.gridDim  = dim3(64, 1, 1);
    cfg.blockDim = dim3(256, 1, 1);
    cudaLaunchAttribute attrs[1];
    attrs[0].id = cudaLaunchAttributeClusterDimension;
    attrs[0].val.clusterDim = {16, 1, 1};
    cfg.attrs = attrs;
    cfg.numAttrs = 1;
    int numClusters = 0;
    cudaError_t qe = cudaOccupancyMaxActiveClusters(
        &numClusters, lstm_cluster_kernel, &cfg);
    bool use_cluster = (qe == cudaSuccess && numClusters >= 4);
    if (!use_cluster) cudaGetLastError();   // clear sticky error

    // 1. Precomputes
    pre0_kernel<<<dim3(4, 128, 4), 256>>>(v_r, v_l, Wih0, bih0, bhh0);
    bsum_kernel<<<8, 256>>>(bih1, bhh1);

    // 2. LSTM layer 0
    if (use_cluster) {
        cudaLaunchKernelEx(&cfg, lstm_cluster_kernel,
                           (const float*)PRE, Whh0, H0);
    } else {
        init_sent_kernel<<<(2 * T_SEQ * 512 + 255) / 256, 256>>>();
        lstm_kernel<<<64, 256>>>(PRE, Whh0, H0);
    }

    // 3. Layer-1 input gates, batched over seq (z=4)
    gemm_kernel<<<dim3(GATES / 128, T_SEQ / 128, 4), 256>>>(
        H0, Wih1, BS, PRE, T_SEQ, GATES, 512, 1.f, 0,
        (long)T_SEQ * 512, (long)GATES * 512, (long)GATES,
        (long)T_SEQ * GATES, 2, 2);

    // 4. LSTM layer 1
    if (use_cluster) {
        cudaLaunchKernelEx(&cfg, lstm_cluster_kernel,
                           (const float*)PRE, Whh1, H1);
    } else {
        lstm_kernel<<<64, 256>>>(PRE, Whh1, H1);
    }

    // 5. MLP encoders, batched over chain (z=2)
    gemm_kernel<<<dim3(D_H1 / 128, T_SEQ / 128, 2), 256>>>(
        H1, W1, b1, FC1, T_SEQ, D_H1, 512, 1.f, 1,
        (long)T_SEQ * 512, 0, 0, (long)T_SEQ * D_H1, 1, 1);

    gemm_kernel<<<dim3(D_H2 / 128, T_SEQ / 128, 2), 256>>>(
        FC1, W2, b2, ENC, T_SEQ, D_H2, D_H1, 1.f, 1,
        (long)T_SEQ * D_H1, 0, 0, (long)T_SEQ * D_H2, 1, 1);

    ws_kernel<<<(D_H3 * D_H2 + 255) / 256, 256>>>(W3);

    // P = 0.5*(enc @ Ws^T + b3)
    gemm_kernel<<<dim3(D_H3 / 128, T_SEQ / 128, 2), 256>>>(
        ENC, WS, b3, PT, T_SEQ, D_H3, D_H2, 0.5f, 0,
        (long)T_SEQ * D_H2, 0, 0, (long)T_SEQ * D_H3, 1, 1);

    // 6. Pair gather + dot + log_softmax
    pair_kernel<<<2048, 256>>>(pair_r, pair_l, Wout, bout, out);
}